// round 5
// baseline (speedup 1.0000x reference)
#include <cuda_runtime.h>
#include <math.h>

#define HID  3072
#define LQ   2048
#define NH   24
#define DH   128
#define N1   21504      // 3*HID + MLP
#define MLPD 12288
#define KF   15360      // HID + MLP
#define LIPN 64
#define CTX  4096
#define EPSV 1e-6f

// ---------------- scratch (static device allocations) ----------------
__device__ float g_sv[HID];
__device__ float g_mod[3 * HID];
__device__ float g_xmod[LQ * HID];
__device__ float g_h[LQ * N1];                 // 44M floats
__device__ float g_qn[NH * LQ * DH];
__device__ float g_qr[NH * LQ * DH];
__device__ float g_kr[NH * LQ * DH];
__device__ float g_vr[NH * LQ * DH];
__device__ float g_attn[LQ * HID];
__device__ float g_ipk[LIPN * HID];
__device__ float g_ipv[LIPN * HID];
__device__ float g_fused[LQ * KF];             // 31.5M floats
__device__ float g_tmp[LQ * HID];

// ---------------- small elementwise kernels ----------------
__global__ void silu_kernel(const float* __restrict__ v, float* __restrict__ sv) {
    int i = blockIdx.x * blockDim.x + threadIdx.x;
    if (i < HID) {
        float x = v[i];
        sv[i] = x / (1.f + __expf(-x));
    }
}

// mod[n] = dot(sv, W[n,:]) + b[n];  W: (9216, 3072) row-major
__global__ void __launch_bounds__(128) mod_gemv(const float* __restrict__ sv,
                                                const float* __restrict__ W,
                                                const float* __restrict__ b,
                                                float* __restrict__ mod) {
    int n = blockIdx.x;
    int tid = threadIdx.x;
    const float* w = W + (size_t)n * HID;
    float s = 0.f;
    for (int i = tid; i < HID; i += 128) s += sv[i] * w[i];
#pragma unroll
    for (int o = 16; o; o >>= 1) s += __shfl_xor_sync(0xffffffffu, s, o);
    __shared__ float red[4];
    if ((tid & 31) == 0) red[tid >> 5] = s;
    __syncthreads();
    if (tid == 0) mod[n] = red[0] + red[1] + red[2] + red[3] + b[n];
}

// per-row layernorm + modulation: xmod = (1+scale)*LN(x) + shift
__global__ void __launch_bounds__(256) ln_mod(const float* __restrict__ x,
                                              const float* __restrict__ mod,
                                              float* __restrict__ xmod) {
    int l = blockIdx.x;
    int tid = threadIdx.x;
    __shared__ float xs[HID];
    __shared__ float red1[8];
    __shared__ float red2[8];
    const float* xr = x + (size_t)l * HID;
    float s = 0.f;
    for (int i = tid; i < HID; i += 256) { float v = xr[i]; xs[i] = v; s += v; }
#pragma unroll
    for (int o = 16; o; o >>= 1) s += __shfl_xor_sync(0xffffffffu, s, o);
    if ((tid & 31) == 0) red1[tid >> 5] = s;
    __syncthreads();
    float tot = 0.f;
#pragma unroll
    for (int i = 0; i < 8; i++) tot += red1[i];
    float mu = tot * (1.f / HID);
    float s2 = 0.f;
    for (int i = tid; i < HID; i += 256) { float d = xs[i] - mu; s2 += d * d; }
#pragma unroll
    for (int o = 16; o; o >>= 1) s2 += __shfl_xor_sync(0xffffffffu, s2, o);
    if ((tid & 31) == 0) red2[tid >> 5] = s2;
    __syncthreads();
    float tot2 = 0.f;
#pragma unroll
    for (int i = 0; i < 8; i++) tot2 += red2[i];
    float rstd = rsqrtf(tot2 * (1.f / HID) + EPSV);
    float* xo = xmod + (size_t)l * HID;
    for (int i = tid; i < HID; i += 256) {
        float nv = (xs[i] - mu) * rstd;
        xo[i] = (1.f + mod[HID + i]) * nv + mod[i];
    }
}

// ---------------- SGEMM: C[M,N] = A[M,K] @ B[N,K]^T + bias ----------------
// 128x128x8 tile, 256 threads, 8x8 per thread. K % 8 == 0, N % 128 == 0.
__global__ void __launch_bounds__(256) sgemm_kernel(int M, int N, int K,
                                                    const float* __restrict__ A,
                                                    const float* __restrict__ B,
                                                    const float* __restrict__ bias,
                                                    float* __restrict__ C) {
    __shared__ float As[8][128];
    __shared__ float Bs[8][128];
    int bm = blockIdx.y * 128;
    int bn = blockIdx.x * 128;
    int tid = threadIdx.x;
    int loadRow = tid >> 1;
    int loadCol = (tid & 1) * 4;
    int tr = (tid / 16) * 8;
    int tc = (tid % 16) * 8;
    float acc[8][8];
#pragma unroll
    for (int i = 0; i < 8; i++)
#pragma unroll
        for (int j = 0; j < 8; j++) acc[i][j] = 0.f;

    const float* Aptr = A + (size_t)(bm + loadRow) * K + loadCol;
    const float* Bptr = B + (size_t)(bn + loadRow) * K + loadCol;
    bool avalid = (bm + loadRow) < M;

    for (int k0 = 0; k0 < K; k0 += 8) {
        float4 a4 = avalid ? *(const float4*)(Aptr + k0) : make_float4(0.f, 0.f, 0.f, 0.f);
        float4 b4 = *(const float4*)(Bptr + k0);
        As[loadCol + 0][loadRow] = a4.x;
        As[loadCol + 1][loadRow] = a4.y;
        As[loadCol + 2][loadRow] = a4.z;
        As[loadCol + 3][loadRow] = a4.w;
        Bs[loadCol + 0][loadRow] = b4.x;
        Bs[loadCol + 1][loadRow] = b4.y;
        Bs[loadCol + 2][loadRow] = b4.z;
        Bs[loadCol + 3][loadRow] = b4.w;
        __syncthreads();
#pragma unroll
        for (int kk = 0; kk < 8; kk++) {
            float4 a0 = *(const float4*)&As[kk][tr];
            float4 a1 = *(const float4*)&As[kk][tr + 4];
            float4 b0 = *(const float4*)&Bs[kk][tc];
            float4 b1 = *(const float4*)&Bs[kk][tc + 4];
            float ra[8] = {a0.x, a0.y, a0.z, a0.w, a1.x, a1.y, a1.z, a1.w};
            float rb[8] = {b0.x, b0.y, b0.z, b0.w, b1.x, b1.y, b1.z, b1.w};
#pragma unroll
            for (int i = 0; i < 8; i++)
#pragma unroll
                for (int j = 0; j < 8; j++) acc[i][j] += ra[i] * rb[j];
        }
        __syncthreads();
    }
    float bv[8];
#pragma unroll
    for (int j = 0; j < 8; j++) bv[j] = bias ? bias[bn + tc + j] : 0.f;
#pragma unroll
    for (int i = 0; i < 8; i++) {
        int row = bm + tr + i;
        if (row < M) {
            float* cr = C + (size_t)row * N + bn + tc;
#pragma unroll
            for (int j = 0; j < 8; j++) cr[j] = acc[i][j] + bv[j];
        }
    }
}

// ---------------- rmsnorm + rope + transpose for q/k/v ----------------
__global__ void __launch_bounds__(128) qkv_prep(const float* __restrict__ h,
                                                const float* __restrict__ pe,
                                                const float* __restrict__ qns,
                                                const float* __restrict__ kns,
                                                float* __restrict__ qn,
                                                float* __restrict__ qr,
                                                float* __restrict__ kr,
                                                float* __restrict__ vr) {
    int head = blockIdx.x;
    int l = blockIdx.y;
    int d = threadIdx.x;
    const float* base = h + (size_t)l * N1 + head * DH;
    float qv = base[d];
    float kv = base[HID + d];
    float vv = base[2 * HID + d];
    float qss = qv * qv, kss = kv * kv;
#pragma unroll
    for (int o = 16; o; o >>= 1) {
        qss += __shfl_xor_sync(0xffffffffu, qss, o);
        kss += __shfl_xor_sync(0xffffffffu, kss, o);
    }
    __shared__ float rq[4], rk[4];
    if ((d & 31) == 0) { rq[d >> 5] = qss; rk[d >> 5] = kss; }
    __syncthreads();
    float qt = rq[0] + rq[1] + rq[2] + rq[3];
    float kt = rk[0] + rk[1] + rk[2] + rk[3];
    float qnv = qv * rsqrtf(qt * (1.f / DH) + EPSV) * qns[d];
    float knv = kv * rsqrtf(kt * (1.f / DH) + EPSV) * kns[d];
    __shared__ float sq[DH], sk[DH];
    sq[d] = qnv; sk[d] = knv;
    __syncthreads();
    int p = d >> 1, r = d & 1;
    const float* per = pe + (((size_t)l * 64 + p) * 2 + r) * 2;
    float qro = per[0] * sq[2 * p] + per[1] * sq[2 * p + 1];
    float kro = per[0] * sk[2 * p] + per[1] * sk[2 * p + 1];
    size_t o = ((size_t)head * LQ + l) * DH + d;
    qn[o] = qnv; qr[o] = qro; kr[o] = kro; vr[o] = vv;
}

// ---------------- flash attention (fp32, online softmax) ----------------
// block = (qtile of 64 rows, head). 256 threads: 4 lanes per q-row, each owns
// a 32-wide chunk of D. K/V tiles of 32 rows live in 32KB static smem.
__global__ void __launch_bounds__(256) flash_kernel(const float* __restrict__ Q,
                                                    const float* __restrict__ Kp,
                                                    const float* __restrict__ Vp,
                                                    int Lk,
                                                    long long kv_head_stride,
                                                    long long kv_row_stride,
                                                    float* __restrict__ Out,
                                                    int accumulate,
                                                    const float* __restrict__ scale_ptr) {
    __shared__ float Ks[32][128];
    __shared__ float Vs[32][128];
    int head = blockIdx.y;
    int qtile = blockIdx.x;
    int tid = threadIdx.x;
    int i = tid >> 2;          // q-row in tile (0..63)
    int g = tid & 3;           // 32-wide D chunk
    int l = qtile * 64 + i;
    const float sm_scale = 0.08838834764831845f;  // 1/sqrt(128)

    float q[32];
    const float* qrow = Q + ((size_t)head * LQ + l) * DH + g * 32;
#pragma unroll
    for (int c = 0; c < 32; c++) q[c] = qrow[c] * sm_scale;

    float m = -INFINITY, lsum = 0.f;
    float acc[32];
#pragma unroll
    for (int c = 0; c < 32; c++) acc[c] = 0.f;

    const float* Kh = Kp + head * kv_head_stride;
    const float* Vh = Vp + head * kv_head_stride;

    for (int kv0 = 0; kv0 < Lk; kv0 += 32) {
        for (int idx = tid; idx < 32 * 32; idx += 256) {
            int r = idx >> 5, c4 = (idx & 31) * 4;
            const float* krow = Kh + (size_t)(kv0 + r) * kv_row_stride;
            const float* vrow = Vh + (size_t)(kv0 + r) * kv_row_stride;
            *(float4*)&Ks[r][c4] = *(const float4*)(krow + c4);
            *(float4*)&Vs[r][c4] = *(const float4*)(vrow + c4);
        }
        __syncthreads();
        for (int j = 0; j < 32; j++) {
            float s = 0.f;
            const float* kr_ = &Ks[j][g * 32];
#pragma unroll
            for (int c = 0; c < 32; c++) s += q[c] * kr_[c];
            s += __shfl_xor_sync(0xffffffffu, s, 1);
            s += __shfl_xor_sync(0xffffffffu, s, 2);
            float mnew = fmaxf(m, s);
            if (mnew > m) {
                float f = __expf(m - mnew);
                lsum *= f;
#pragma unroll
                for (int c = 0; c < 32; c++) acc[c] *= f;
                m = mnew;
            }
            float p = __expf(s - m);
            lsum += p;
            const float* vr_ = &Vs[j][g * 32];
#pragma unroll
            for (int c = 0; c < 32; c++) acc[c] += p * vr_[c];
        }
        __syncthreads();
    }
    float inv = 1.f / lsum;
    float* orow = Out + (size_t)l * HID + head * DH + g * 32;
    if (accumulate) {
        float sc = *scale_ptr;
#pragma unroll
        for (int c = 0; c < 32; c++) orow[c] += sc * acc[c] * inv;
    } else {
#pragma unroll
        for (int c = 0; c < 32; c++) orow[c] = acc[c] * inv;
    }
}

// ---------------- build fused = [attn_out, gelu(mlp)] ----------------
__global__ void fuse_gelu(const float* __restrict__ attn,
                          const float* __restrict__ h,
                          float* __restrict__ fused) {
    size_t idx = (size_t)blockIdx.x * blockDim.x + threadIdx.x;
    if (idx >= (size_t)LQ * KF) return;
    int l = (int)(idx / KF);
    int j = (int)(idx % KF);
    float f;
    if (j < HID) {
        f = attn[(size_t)l * HID + j];
    } else {
        float v = h[(size_t)l * N1 + 3 * HID + (j - HID)];
        float v3 = v * v * v;
        f = 0.5f * v * (1.f + tanhf(0.7978845608028654f * (v + 0.044715f * v3)));
    }
    fused[idx] = f;
}

// ---------------- residual: out = x + gate * tmp ----------------
__global__ void final_kernel(const float* __restrict__ x,
                             const float* __restrict__ mod,
                             const float* __restrict__ tmp,
                             float* __restrict__ out) {
    size_t idx = (size_t)blockIdx.x * blockDim.x + threadIdx.x;
    if (idx >= (size_t)LQ * HID) return;
    int c = (int)(idx % HID);
    out[idx] = x[idx] + mod[2 * HID + c] * tmp[idx];
}

// ---------------- launch ----------------
extern "C" void kernel_launch(void* const* d_in, const int* in_sizes, int n_in,
                              void* d_out, int out_size) {
    const float* x          = (const float*)d_in[0];
    const float* vec        = (const float*)d_in[1];
    const float* pe         = (const float*)d_in[2];
    const float* image_proj = (const float*)d_in[3];
    const float* ip_scale   = (const float*)d_in[4];
    const float* mod_w      = (const float*)d_in[5];
    const float* mod_b      = (const float*)d_in[6];
    const float* w1         = (const float*)d_in[7];
    const float* b1         = (const float*)d_in[8];
    const float* w2         = (const float*)d_in[9];
    const float* b2         = (const float*)d_in[10];
    const float* qns        = (const float*)d_in[11];
    const float* kns        = (const float*)d_in[12];
    const float* ipkw       = (const float*)d_in[13];
    const float* ipvw       = (const float*)d_in[14];
    float* out = (float*)d_out;

    float *sv, *mod, *xmod, *h, *qn, *qr, *kr, *vr, *attn, *ipk, *ipv, *fused, *tmp;
    cudaGetSymbolAddress((void**)&sv, g_sv);
    cudaGetSymbolAddress((void**)&mod, g_mod);
    cudaGetSymbolAddress((void**)&xmod, g_xmod);
    cudaGetSymbolAddress((void**)&h, g_h);
    cudaGetSymbolAddress((void**)&qn, g_qn);
    cudaGetSymbolAddress((void**)&qr, g_qr);
    cudaGetSymbolAddress((void**)&kr, g_kr);
    cudaGetSymbolAddress((void**)&vr, g_vr);
    cudaGetSymbolAddress((void**)&attn, g_attn);
    cudaGetSymbolAddress((void**)&ipk, g_ipk);
    cudaGetSymbolAddress((void**)&ipv, g_ipv);
    cudaGetSymbolAddress((void**)&fused, g_fused);
    cudaGetSymbolAddress((void**)&tmp, g_tmp);

    silu_kernel<<<12, 256>>>(vec, sv);
    mod_gemv<<<3 * HID, 128>>>(sv, mod_w, mod_b, mod);
    ln_mod<<<LQ, 256>>>(x, mod, xmod);

    // h = x_mod @ W1^T + b1  : (2048, 21504)
    sgemm_kernel<<<dim3(N1 / 128, LQ / 128), 256>>>(LQ, N1, HID, xmod, w1, b1, h);

    qkv_prep<<<dim3(NH, LQ), 128>>>(h, pe, qns, kns, qn, qr, kr, vr);

    // ip_k / ip_v : (64, 3072) = image_proj @ W^T
    sgemm_kernel<<<dim3(HID / 128, 1), 256>>>(LIPN, HID, CTX, image_proj, ipkw, nullptr, ipk);
    sgemm_kernel<<<dim3(HID / 128, 1), 256>>>(LIPN, HID, CTX, image_proj, ipvw, nullptr, ipv);

    // self-attention (roped q/k), writes attn_out
    flash_kernel<<<dim3(LQ / 64, NH), 256>>>(qr, kr, vr, LQ,
                                             (long long)LQ * DH, (long long)DH,
                                             attn, 0, nullptr);
    // ip attention (un-roped q vs ip_k/ip_v), accumulates ip_scale * result
    flash_kernel<<<dim3(LQ / 64, NH), 256>>>(qn, ipk, ipv, LIPN,
                                             (long long)DH, (long long)HID,
                                             attn, 1, ip_scale);

    fuse_gelu<<<(LQ * KF + 255) / 256, 256>>>(attn, h, fused);

    // out_tmp = fused @ W2^T + b2 : (2048, 3072)
    sgemm_kernel<<<dim3(HID / 128, LQ / 128), 256>>>(LQ, HID, KF, fused, w2, b2, tmp);

    final_kernel<<<(LQ * HID + 255) / 256, 256>>>(x, mod, tmp, out);
}

// round 7
// speedup vs baseline: 1.4296x; 1.4296x over previous
#include <cuda_runtime.h>
#include <cuda_bf16.h>
#include <cstdint>
#include <math.h>

#define HID  3072
#define LQ   2048
#define NH   24
#define DH   128
#define N1   21504      // 3*HID + MLP
#define MLPD 12288
#define KF   15360      // HID + MLP
#define LIPN 64
#define CTX  4096
#define EPSV 1e-6f

// ---------------- scratch (static device allocations) ----------------
__device__ float g_sv[HID];
__device__ float g_mod[3 * HID];
__device__ float g_h[LQ * N1];
__device__ float g_qn[NH * LQ * DH];
__device__ float g_qr[NH * LQ * DH];
__device__ float g_kr[NH * LQ * DH];
__device__ float g_vr[NH * LQ * DH];
__device__ float g_attn[LQ * HID];
__device__ float g_ipk[LIPN * HID];
__device__ float g_ipv[LIPN * HID];
__device__ float g_tmp[LQ * HID];

// bf16 split operands (hi / lo)
__device__ __nv_bfloat16 g_xmh[LQ * HID],   g_xml[LQ * HID];
__device__ __nv_bfloat16 g_w1h[N1 * HID],   g_w1l[N1 * HID];
__device__ __nv_bfloat16 g_w2h[HID * KF],   g_w2l[HID * KF];
__device__ __nv_bfloat16 g_fuh[LQ * KF],    g_ful[LQ * KF];
__device__ __nv_bfloat16 g_iph[LIPN * CTX], g_ipl[LIPN * CTX];
__device__ __nv_bfloat16 g_ipkh[HID * CTX], g_ipkl[HID * CTX];
__device__ __nv_bfloat16 g_ipvh[HID * CTX], g_ipvl[HID * CTX];

// ---------------- split fp32 -> bf16 hi + bf16 lo ----------------
__global__ void split_bf16(const float* __restrict__ src,
                           __nv_bfloat16* __restrict__ hi,
                           __nv_bfloat16* __restrict__ lo, size_t n) {
    size_t i = (size_t)blockIdx.x * blockDim.x + threadIdx.x;
    if (i >= n) return;
    float x = src[i];
    __nv_bfloat16 h = __float2bfloat16(x);
    hi[i] = h;
    lo[i] = __float2bfloat16(x - __bfloat162float(h));
}

// ---------------- small elementwise kernels ----------------
__global__ void silu_kernel(const float* __restrict__ v, float* __restrict__ sv) {
    int i = blockIdx.x * blockDim.x + threadIdx.x;
    if (i < HID) {
        float x = v[i];
        sv[i] = x / (1.f + __expf(-x));
    }
}

__global__ void __launch_bounds__(128) mod_gemv(const float* __restrict__ sv,
                                                const float* __restrict__ W,
                                                const float* __restrict__ b,
                                                float* __restrict__ mod) {
    int n = blockIdx.x;
    int tid = threadIdx.x;
    const float* w = W + (size_t)n * HID;
    float s = 0.f;
    for (int i = tid; i < HID; i += 128) s += sv[i] * w[i];
#pragma unroll
    for (int o = 16; o; o >>= 1) s += __shfl_xor_sync(0xffffffffu, s, o);
    __shared__ float red[4];
    if ((tid & 31) == 0) red[tid >> 5] = s;
    __syncthreads();
    if (tid == 0) mod[n] = red[0] + red[1] + red[2] + red[3] + b[n];
}

// layernorm + modulation, writes bf16 hi/lo directly (GEMM A operand)
__global__ void __launch_bounds__(256) ln_mod(const float* __restrict__ x,
                                              const float* __restrict__ mod,
                                              __nv_bfloat16* __restrict__ xh,
                                              __nv_bfloat16* __restrict__ xl) {
    int l = blockIdx.x;
    int tid = threadIdx.x;
    __shared__ float xs[HID];
    __shared__ float red1[8];
    __shared__ float red2[8];
    const float* xr = x + (size_t)l * HID;
    float s = 0.f;
    for (int i = tid; i < HID; i += 256) { float v = xr[i]; xs[i] = v; s += v; }
#pragma unroll
    for (int o = 16; o; o >>= 1) s += __shfl_xor_sync(0xffffffffu, s, o);
    if ((tid & 31) == 0) red1[tid >> 5] = s;
    __syncthreads();
    float tot = 0.f;
#pragma unroll
    for (int i = 0; i < 8; i++) tot += red1[i];
    float mu = tot * (1.f / HID);
    float s2 = 0.f;
    for (int i = tid; i < HID; i += 256) { float d = xs[i] - mu; s2 += d * d; }
#pragma unroll
    for (int o = 16; o; o >>= 1) s2 += __shfl_xor_sync(0xffffffffu, s2, o);
    if ((tid & 31) == 0) red2[tid >> 5] = s2;
    __syncthreads();
    float tot2 = 0.f;
#pragma unroll
    for (int i = 0; i < 8; i++) tot2 += red2[i];
    float rstd = rsqrtf(tot2 * (1.f / HID) + EPSV);
    for (int i = tid; i < HID; i += 256) {
        float nv = (xs[i] - mu) * rstd;
        float v = (1.f + mod[HID + i]) * nv + mod[i];
        __nv_bfloat16 h = __float2bfloat16(v);
        size_t o = (size_t)l * HID + i;
        xh[o] = h;
        xl[o] = __float2bfloat16(v - __bfloat162float(h));
    }
}

// ---------------- tensor-core GEMM: C = A @ B^T (+bias) ----------------
// bf16 split: C = Ah@Bh + Ah@Bl + Al@Bh, fp32 accumulate.
// A: M x K (hi/lo bf16), B: N x K (hi/lo bf16). 128x128x32 CTA tile,
// 8 warps (4x2), warp tile 32x64 via m16n8k16 mma.
#define MMA16816(d, a, b0, b1)                                               \
    asm volatile(                                                            \
        "mma.sync.aligned.m16n8k16.row.col.f32.bf16.bf16.f32 "               \
        "{%0,%1,%2,%3}, {%4,%5,%6,%7}, {%8,%9}, {%0,%1,%2,%3};"              \
        : "+f"(d[0]), "+f"(d[1]), "+f"(d[2]), "+f"(d[3])                     \
        : "r"(a[0]), "r"(a[1]), "r"(a[2]), "r"(a[3]), "r"(b0), "r"(b1))

#define BKP 40   // padded k-stride (bf16) -> conflict-free fragment LDS

__global__ void __launch_bounds__(256) mma_gemm(int M, int N, int K,
                                                const __nv_bfloat16* __restrict__ Ah,
                                                const __nv_bfloat16* __restrict__ Al,
                                                const __nv_bfloat16* __restrict__ Bh,
                                                const __nv_bfloat16* __restrict__ Bl,
                                                const float* __restrict__ bias,
                                                float* __restrict__ C) {
    __shared__ __nv_bfloat16 sAh[128][BKP];
    __shared__ __nv_bfloat16 sAl[128][BKP];
    __shared__ __nv_bfloat16 sBh[128][BKP];
    __shared__ __nv_bfloat16 sBl[128][BKP];

    int bm = blockIdx.y * 128;
    int bn = blockIdx.x * 128;
    int tid = threadIdx.x;
    int warp = tid >> 5, lane = tid & 31;
    int wm = (warp & 3) * 32;       // warp M offset
    int wn = (warp >> 2) * 64;      // warp N offset
    int g = lane >> 2;              // group id (0..7)
    int tg = lane & 3;              // thread in group

    float acc[2][8][4];
#pragma unroll
    for (int mt = 0; mt < 2; mt++)
#pragma unroll
        for (int nt = 0; nt < 8; nt++)
#pragma unroll
            for (int r = 0; r < 4; r++) acc[mt][nt][r] = 0.f;

    const int4 zero4 = make_int4(0, 0, 0, 0);

    for (int kt = 0; kt < K; kt += 32) {
#pragma unroll
        for (int j = 0; j < 2; j++) {
            int idx = tid + j * 256;
            int row = idx >> 2;          // 0..127
            int seg = (idx & 3) * 8;     // 0,8,16,24 (bf16)
            int arow = bm + row;
            int4 vah, val;
            if (arow < M) {
                vah = *(const int4*)(Ah + (size_t)arow * K + kt + seg);
                val = *(const int4*)(Al + (size_t)arow * K + kt + seg);
            } else { vah = zero4; val = zero4; }
            *(int4*)&sAh[row][seg] = vah;
            *(int4*)&sAl[row][seg] = val;
            int brow = bn + row;
            *(int4*)&sBh[row][seg] = *(const int4*)(Bh + (size_t)brow * K + kt + seg);
            *(int4*)&sBl[row][seg] = *(const int4*)(Bl + (size_t)brow * K + kt + seg);
        }
        __syncthreads();
#pragma unroll
        for (int kk = 0; kk < 32; kk += 16) {
            uint32_t ah[2][4], al[2][4];
            int c = kk + 2 * tg;
#pragma unroll
            for (int mt = 0; mt < 2; mt++) {
                int r = wm + mt * 16 + g;
                ah[mt][0] = *(const uint32_t*)&sAh[r][c];
                ah[mt][1] = *(const uint32_t*)&sAh[r + 8][c];
                ah[mt][2] = *(const uint32_t*)&sAh[r][c + 8];
                ah[mt][3] = *(const uint32_t*)&sAh[r + 8][c + 8];
                al[mt][0] = *(const uint32_t*)&sAl[r][c];
                al[mt][1] = *(const uint32_t*)&sAl[r + 8][c];
                al[mt][2] = *(const uint32_t*)&sAl[r][c + 8];
                al[mt][3] = *(const uint32_t*)&sAl[r + 8][c + 8];
            }
#pragma unroll
            for (int nt = 0; nt < 8; nt++) {
                int n = wn + nt * 8 + g;
                uint32_t bh0 = *(const uint32_t*)&sBh[n][c];
                uint32_t bh1 = *(const uint32_t*)&sBh[n][c + 8];
                uint32_t bl0 = *(const uint32_t*)&sBl[n][c];
                uint32_t bl1 = *(const uint32_t*)&sBl[n][c + 8];
#pragma unroll
                for (int mt = 0; mt < 2; mt++) {
                    MMA16816(acc[mt][nt], ah[mt], bh0, bh1);
                    MMA16816(acc[mt][nt], ah[mt], bl0, bl1);
                    MMA16816(acc[mt][nt], al[mt], bh0, bh1);
                }
            }
        }
        __syncthreads();
    }

    // epilogue
#pragma unroll
    for (int mt = 0; mt < 2; mt++) {
#pragma unroll
        for (int nt = 0; nt < 8; nt++) {
            int col = bn + wn + nt * 8 + 2 * tg;
            float bv0 = bias ? bias[col] : 0.f;
            float bv1 = bias ? bias[col + 1] : 0.f;
            int row0 = bm + wm + mt * 16 + g;
            if (row0 < M) {
                float2* p = (float2*)(C + (size_t)row0 * N + col);
                *p = make_float2(acc[mt][nt][0] + bv0, acc[mt][nt][1] + bv1);
            }
            int row1 = row0 + 8;
            if (row1 < M) {
                float2* p = (float2*)(C + (size_t)row1 * N + col);
                *p = make_float2(acc[mt][nt][2] + bv0, acc[mt][nt][3] + bv1);
            }
        }
    }
}

// ---------------- rmsnorm + rope + transpose for q/k/v ----------------
__global__ void __launch_bounds__(128) qkv_prep(const float* __restrict__ h,
                                                const float* __restrict__ pe,
                                                const float* __restrict__ qns,
                                                const float* __restrict__ kns,
                                                float* __restrict__ qn,
                                                float* __restrict__ qr,
                                                float* __restrict__ kr,
                                                float* __restrict__ vr) {
    int head = blockIdx.x;
    int l = blockIdx.y;
    int d = threadIdx.x;
    const float* base = h + (size_t)l * N1 + head * DH;
    float qv = base[d];
    float kv = base[HID + d];
    float vv = base[2 * HID + d];
    float qss = qv * qv, kss = kv * kv;
#pragma unroll
    for (int o = 16; o; o >>= 1) {
        qss += __shfl_xor_sync(0xffffffffu, qss, o);
        kss += __shfl_xor_sync(0xffffffffu, kss, o);
    }
    __shared__ float rq[4], rk[4];
    if ((d & 31) == 0) { rq[d >> 5] = qss; rk[d >> 5] = kss; }
    __syncthreads();
    float qt = rq[0] + rq[1] + rq[2] + rq[3];
    float kt = rk[0] + rk[1] + rk[2] + rk[3];
    float qnv = qv * rsqrtf(qt * (1.f / DH) + EPSV) * qns[d];
    float knv = kv * rsqrtf(kt * (1.f / DH) + EPSV) * kns[d];
    __shared__ float sq[DH], sk[DH];
    sq[d] = qnv; sk[d] = knv;
    __syncthreads();
    int p = d >> 1, r = d & 1;
    const float* per = pe + (((size_t)l * 64 + p) * 2 + r) * 2;
    float qro = per[0] * sq[2 * p] + per[1] * sq[2 * p + 1];
    float kro = per[0] * sk[2 * p] + per[1] * sk[2 * p + 1];
    size_t o = ((size_t)head * LQ + l) * DH + d;
    qn[o] = qnv; qr[o] = qro; kr[o] = kro; vr[o] = vv;
}

// ---------------- flash attention (fp32, online softmax) ----------------
__global__ void __launch_bounds__(256) flash_kernel(const float* __restrict__ Q,
                                                    const float* __restrict__ Kp,
                                                    const float* __restrict__ Vp,
                                                    int Lk,
                                                    long long kv_head_stride,
                                                    long long kv_row_stride,
                                                    float* __restrict__ Out,
                                                    int accumulate,
                                                    const float* __restrict__ scale_ptr) {
    __shared__ float Ks[32][128];
    __shared__ float Vs[32][128];
    int head = blockIdx.y;
    int qtile = blockIdx.x;
    int tid = threadIdx.x;
    int i = tid >> 2;
    int g = tid & 3;
    int l = qtile * 64 + i;
    const float sm_scale = 0.08838834764831845f;

    float q[32];
    const float* qrow = Q + ((size_t)head * LQ + l) * DH + g * 32;
#pragma unroll
    for (int c = 0; c < 32; c++) q[c] = qrow[c] * sm_scale;

    float m = -INFINITY, lsum = 0.f;
    float acc[32];
#pragma unroll
    for (int c = 0; c < 32; c++) acc[c] = 0.f;

    const float* Kh = Kp + head * kv_head_stride;
    const float* Vh = Vp + head * kv_head_stride;

    for (int kv0 = 0; kv0 < Lk; kv0 += 32) {
        for (int idx = tid; idx < 32 * 32; idx += 256) {
            int r = idx >> 5, c4 = (idx & 31) * 4;
            const float* krow = Kh + (size_t)(kv0 + r) * kv_row_stride;
            const float* vrow = Vh + (size_t)(kv0 + r) * kv_row_stride;
            *(float4*)&Ks[r][c4] = *(const float4*)(krow + c4);
            *(float4*)&Vs[r][c4] = *(const float4*)(vrow + c4);
        }
        __syncthreads();
        for (int j = 0; j < 32; j++) {
            float s = 0.f;
            const float* kr_ = &Ks[j][g * 32];
#pragma unroll
            for (int c = 0; c < 32; c++) s += q[c] * kr_[c];
            s += __shfl_xor_sync(0xffffffffu, s, 1);
            s += __shfl_xor_sync(0xffffffffu, s, 2);
            float mnew = fmaxf(m, s);
            if (mnew > m) {
                float f = __expf(m - mnew);
                lsum *= f;
#pragma unroll
                for (int c = 0; c < 32; c++) acc[c] *= f;
                m = mnew;
            }
            float p = __expf(s - m);
            lsum += p;
            const float* vr_ = &Vs[j][g * 32];
#pragma unroll
            for (int c = 0; c < 32; c++) acc[c] += p * vr_[c];
        }
        __syncthreads();
    }
    float inv = 1.f / lsum;
    float* orow = Out + (size_t)l * HID + head * DH + g * 32;
    if (accumulate) {
        float sc = *scale_ptr;
#pragma unroll
        for (int c = 0; c < 32; c++) orow[c] += sc * acc[c] * inv;
    } else {
#pragma unroll
        for (int c = 0; c < 32; c++) orow[c] = acc[c] * inv;
    }
}

// ---------------- fused = [attn_out, gelu(mlp)] -> bf16 hi/lo ----------------
__global__ void fuse_gelu(const float* __restrict__ attn,
                          const float* __restrict__ h,
                          __nv_bfloat16* __restrict__ fh,
                          __nv_bfloat16* __restrict__ fl) {
    size_t idx = (size_t)blockIdx.x * blockDim.x + threadIdx.x;
    if (idx >= (size_t)LQ * KF) return;
    int l = (int)(idx / KF);
    int j = (int)(idx % KF);
    float f;
    if (j < HID) {
        f = attn[(size_t)l * HID + j];
    } else {
        float v = h[(size_t)l * N1 + 3 * HID + (j - HID)];
        float v3 = v * v * v;
        f = 0.5f * v * (1.f + tanhf(0.7978845608028654f * (v + 0.044715f * v3)));
    }
    __nv_bfloat16 hh = __float2bfloat16(f);
    fh[idx] = hh;
    fl[idx] = __float2bfloat16(f - __bfloat162float(hh));
}

// ---------------- residual: out = x + gate * tmp ----------------
__global__ void final_kernel(const float* __restrict__ x,
                             const float* __restrict__ mod,
                             const float* __restrict__ tmp,
                             float* __restrict__ out) {
    size_t idx = (size_t)blockIdx.x * blockDim.x + threadIdx.x;
    if (idx >= (size_t)LQ * HID) return;
    int c = (int)(idx % HID);
    out[idx] = x[idx] + mod[2 * HID + c] * tmp[idx];
}

// ---------------- launch ----------------
extern "C" void kernel_launch(void* const* d_in, const int* in_sizes, int n_in,
                              void* d_out, int out_size) {
    const float* x          = (const float*)d_in[0];
    const float* vec        = (const float*)d_in[1];
    const float* pe         = (const float*)d_in[2];
    const float* image_proj = (const float*)d_in[3];
    const float* ip_scale   = (const float*)d_in[4];
    const float* mod_w      = (const float*)d_in[5];
    const float* mod_b      = (const float*)d_in[6];
    const float* w1         = (const float*)d_in[7];
    const float* b1         = (const float*)d_in[8];
    const float* w2         = (const float*)d_in[9];
    const float* b2         = (const float*)d_in[10];
    const float* qns        = (const float*)d_in[11];
    const float* kns        = (const float*)d_in[12];
    const float* ipkw       = (const float*)d_in[13];
    const float* ipvw       = (const float*)d_in[14];
    float* out = (float*)d_out;

    float *sv, *mod, *h, *qn, *qr, *kr, *vr, *attn, *ipk, *ipv, *tmp;
    __nv_bfloat16 *xmh, *xml, *w1h, *w1l, *w2h, *w2l, *fuh, *ful;
    __nv_bfloat16 *iph, *ipl, *ipkh, *ipkl, *ipvh, *ipvl;
    cudaGetSymbolAddress((void**)&sv, g_sv);
    cudaGetSymbolAddress((void**)&mod, g_mod);
    cudaGetSymbolAddress((void**)&h, g_h);
    cudaGetSymbolAddress((void**)&qn, g_qn);
    cudaGetSymbolAddress((void**)&qr, g_qr);
    cudaGetSymbolAddress((void**)&kr, g_kr);
    cudaGetSymbolAddress((void**)&vr, g_vr);
    cudaGetSymbolAddress((void**)&attn, g_attn);
    cudaGetSymbolAddress((void**)&ipk, g_ipk);
    cudaGetSymbolAddress((void**)&ipv, g_ipv);
    cudaGetSymbolAddress((void**)&tmp, g_tmp);
    cudaGetSymbolAddress((void**)&xmh, g_xmh);
    cudaGetSymbolAddress((void**)&xml, g_xml);
    cudaGetSymbolAddress((void**)&w1h, g_w1h);
    cudaGetSymbolAddress((void**)&w1l, g_w1l);
    cudaGetSymbolAddress((void**)&w2h, g_w2h);
    cudaGetSymbolAddress((void**)&w2l, g_w2l);
    cudaGetSymbolAddress((void**)&fuh, g_fuh);
    cudaGetSymbolAddress((void**)&ful, g_ful);
    cudaGetSymbolAddress((void**)&iph, g_iph);
    cudaGetSymbolAddress((void**)&ipl, g_ipl);
    cudaGetSymbolAddress((void**)&ipkh, g_ipkh);
    cudaGetSymbolAddress((void**)&ipkl, g_ipkl);
    cudaGetSymbolAddress((void**)&ipvh, g_ipvh);
    cudaGetSymbolAddress((void**)&ipvl, g_ipvl);

    silu_kernel<<<12, 256>>>(vec, sv);
    mod_gemv<<<3 * HID, 128>>>(sv, mod_w, mod_b, mod);
    ln_mod<<<LQ, 256>>>(x, mod, xmh, xml);

    // split weights / activations to bf16 hi+lo
    {
        size_t n;
        n = (size_t)N1 * HID;
        split_bf16<<<(unsigned)((n + 255) / 256), 256>>>(w1, w1h, w1l, n);
        n = (size_t)HID * KF;
        split_bf16<<<(unsigned)((n + 255) / 256), 256>>>(w2, w2h, w2l, n);
        n = (size_t)LIPN * CTX;
        split_bf16<<<(unsigned)((n + 255) / 256), 256>>>(image_proj, iph, ipl, n);
        n = (size_t)HID * CTX;
        split_bf16<<<(unsigned)((n + 255) / 256), 256>>>(ipkw, ipkh, ipkl, n);
        split_bf16<<<(unsigned)((n + 255) / 256), 256>>>(ipvw, ipvh, ipvl, n);
    }

    // h = x_mod @ W1^T + b1 : (2048, 21504), K=3072
    mma_gemm<<<dim3(N1 / 128, LQ / 128), 256>>>(LQ, N1, HID, xmh, xml, w1h, w1l, b1, h);

    qkv_prep<<<dim3(NH, LQ), 128>>>(h, pe, qns, kns, qn, qr, kr, vr);

    // ip_k / ip_v : (64, 3072) = image_proj @ W^T, K=4096
    mma_gemm<<<dim3(HID / 128, 1), 256>>>(LIPN, HID, CTX, iph, ipl, ipkh, ipkl, nullptr, ipk);
    mma_gemm<<<dim3(HID / 128, 1), 256>>>(LIPN, HID, CTX, iph, ipl, ipvh, ipvl, nullptr, ipv);

    // self-attention (roped q/k)
    flash_kernel<<<dim3(LQ / 64, NH), 256>>>(qr, kr, vr, LQ,
                                             (long long)LQ * DH, (long long)DH,
                                             attn, 0, nullptr);
    // ip attention (un-roped q vs ip_k/ip_v), accumulates ip_scale * result
    flash_kernel<<<dim3(LQ / 64, NH), 256>>>(qn, ipk, ipv, LIPN,
                                             (long long)DH, (long long)HID,
                                             attn, 1, ip_scale);

    fuse_gelu<<<(LQ * KF + 255) / 256, 256>>>(attn, h, fuh, ful);

    // out_tmp = fused @ W2^T + b2 : (2048, 3072), K=15360
    mma_gemm<<<dim3(HID / 128, LQ / 128), 256>>>(LQ, HID, KF, fuh, ful, w2h, w2l, b2, tmp);

    final_kernel<<<(LQ * HID + 255) / 256, 256>>>(x, mod, tmp, out);
}

// round 11
// speedup vs baseline: 1.5218x; 1.0645x over previous
#include <cuda_runtime.h>
#include <cuda_bf16.h>
#include <cstdint>
#include <math.h>

#define HID  3072
#define LQ   2048
#define NH   24
#define DH   128
#define N1   21504      // 3*HID + MLP
#define MLPD 12288
#define KF   15360      // HID + MLP
#define LIPN 64
#define CTX  4096
#define EPSV 1e-6f

// ---------------- scratch (static device allocations) ----------------
__device__ float g_sv[HID];
__device__ float g_mod[3 * HID];
__device__ float g_h[LQ * N1];
__device__ float g_qn[NH * LQ * DH];
__device__ float g_qr[NH * LQ * DH];
__device__ float g_kr[NH * LQ * DH];
__device__ float g_vr[NH * LQ * DH];
__device__ float g_attn[LQ * HID];
__device__ float g_ipk[LIPN * HID];
__device__ float g_ipv[LIPN * HID];
__device__ float g_tmp[LQ * HID];

// bf16 split operands (hi / lo)
__device__ __nv_bfloat16 g_xmh[LQ * HID],   g_xml[LQ * HID];
__device__ __nv_bfloat16 g_w1h[N1 * HID],   g_w1l[N1 * HID];
__device__ __nv_bfloat16 g_w2h[HID * KF],   g_w2l[HID * KF];
__device__ __nv_bfloat16 g_fuh[LQ * KF],    g_ful[LQ * KF];
__device__ __nv_bfloat16 g_iph[LIPN * CTX], g_ipl[LIPN * CTX];
__device__ __nv_bfloat16 g_ipkh[HID * CTX], g_ipkl[HID * CTX];
__device__ __nv_bfloat16 g_ipvh[HID * CTX], g_ipvl[HID * CTX];

// ---------------- split fp32 -> bf16 hi + bf16 lo (vectorized) ----------------
__global__ void split_bf16_v4(const float4* __restrict__ src,
                              __nv_bfloat162* __restrict__ hi,
                              __nv_bfloat162* __restrict__ lo, size_t n4) {
    size_t i = (size_t)blockIdx.x * blockDim.x + threadIdx.x;
    if (i >= n4) return;
    float4 v = src[i];
    __nv_bfloat16 h0 = __float2bfloat16(v.x);
    __nv_bfloat16 h1 = __float2bfloat16(v.y);
    __nv_bfloat16 h2 = __float2bfloat16(v.z);
    __nv_bfloat16 h3 = __float2bfloat16(v.w);
    hi[2 * i]     = __nv_bfloat162(h0, h1);
    hi[2 * i + 1] = __nv_bfloat162(h2, h3);
    lo[2 * i]     = __nv_bfloat162(__float2bfloat16(v.x - __bfloat162float(h0)),
                                   __float2bfloat16(v.y - __bfloat162float(h1)));
    lo[2 * i + 1] = __nv_bfloat162(__float2bfloat16(v.z - __bfloat162float(h2)),
                                   __float2bfloat16(v.w - __bfloat162float(h3)));
}

// ---------------- small elementwise kernels ----------------
__global__ void silu_kernel(const float* __restrict__ v, float* __restrict__ sv) {
    int i = blockIdx.x * blockDim.x + threadIdx.x;
    if (i < HID) {
        float x = v[i];
        sv[i] = x / (1.f + __expf(-x));
    }
}

__global__ void __launch_bounds__(128) mod_gemv(const float* __restrict__ sv,
                                                const float* __restrict__ W,
                                                const float* __restrict__ b,
                                                float* __restrict__ mod) {
    int n = blockIdx.x;
    int tid = threadIdx.x;
    const float* w = W + (size_t)n * HID;
    float s = 0.f;
    for (int i = tid; i < HID; i += 128) s += sv[i] * w[i];
#pragma unroll
    for (int o = 16; o; o >>= 1) s += __shfl_xor_sync(0xffffffffu, s, o);
    __shared__ float red[4];
    if ((tid & 31) == 0) red[tid >> 5] = s;
    __syncthreads();
    if (tid == 0) mod[n] = red[0] + red[1] + red[2] + red[3] + b[n];
}

// layernorm + modulation, writes bf16 hi/lo directly (GEMM A operand)
__global__ void __launch_bounds__(256) ln_mod(const float* __restrict__ x,
                                              const float* __restrict__ mod,
                                              __nv_bfloat16* __restrict__ xh,
                                              __nv_bfloat16* __restrict__ xl) {
    int l = blockIdx.x;
    int tid = threadIdx.x;
    __shared__ float xs[HID];
    __shared__ float red1[8];
    __shared__ float red2[8];
    const float* xr = x + (size_t)l * HID;
    float s = 0.f;
    for (int i = tid; i < HID; i += 256) { float v = xr[i]; xs[i] = v; s += v; }
#pragma unroll
    for (int o = 16; o; o >>= 1) s += __shfl_xor_sync(0xffffffffu, s, o);
    if ((tid & 31) == 0) red1[tid >> 5] = s;
    __syncthreads();
    float tot = 0.f;
#pragma unroll
    for (int i = 0; i < 8; i++) tot += red1[i];
    float mu = tot * (1.f / HID);
    float s2 = 0.f;
    for (int i = tid; i < HID; i += 256) { float d = xs[i] - mu; s2 += d * d; }
#pragma unroll
    for (int o = 16; o; o >>= 1) s2 += __shfl_xor_sync(0xffffffffu, s2, o);
    if ((tid & 31) == 0) red2[tid >> 5] = s2;
    __syncthreads();
    float tot2 = 0.f;
#pragma unroll
    for (int i = 0; i < 8; i++) tot2 += red2[i];
    float rstd = rsqrtf(tot2 * (1.f / HID) + EPSV);
    for (int i = tid; i < HID; i += 256) {
        float nv = (xs[i] - mu) * rstd;
        float v = (1.f + mod[HID + i]) * nv + mod[i];
        __nv_bfloat16 h = __float2bfloat16(v);
        size_t o = (size_t)l * HID + i;
        xh[o] = h;
        xl[o] = __float2bfloat16(v - __bfloat162float(h));
    }
}

// ---------------- tensor-core GEMM (pipelined) ----------------
// C = A @ B^T (+bias), bf16 split: Ah@Bh + Ah@Bl + Al@Bh, fp32 acc.
// 128x64x32 CTA tile, 8 warps (4x2 -> warp tile 32x32), 2-stage cp.async,
// ldmatrix.x4 fragments, XOR-swizzled smem (conflict-free).
#define MMA16816(d, a, b0, b1)                                               \
    asm volatile(                                                            \
        "mma.sync.aligned.m16n8k16.row.col.f32.bf16.bf16.f32 "               \
        "{%0,%1,%2,%3}, {%4,%5,%6,%7}, {%8,%9}, {%0,%1,%2,%3};"              \
        : "+f"(d[0]), "+f"(d[1]), "+f"(d[2]), "+f"(d[3])                     \
        : "r"(a[0]), "r"(a[1]), "r"(a[2]), "r"(a[3]), "r"(b0), "r"(b1))

#define LDSM4(R, addr)                                                       \
    asm volatile("ldmatrix.sync.aligned.m8n8.x4.shared.b16 {%0,%1,%2,%3}, [%4];" \
        : "=r"((R)[0]), "=r"((R)[1]), "=r"((R)[2]), "=r"((R)[3]) : "r"(addr))

// per-stage byte offsets: Ah 0, Al 8192, Bh 16384, Bl 20480; stage stride 24576
#define STG_BYTES 24576
#define OFF_AH 0
#define OFF_AL 8192
#define OFF_BH 16384
#define OFF_BL 20480

// row = tile row, chunk = 16B column chunk (k/8). 64B rows, XOR swizzle.
__device__ __forceinline__ uint32_t swz(int row, int chunk) {
    return (uint32_t)(row * 64 + ((chunk ^ ((row >> 1) & 3)) << 4));
}

__device__ __forceinline__ void cp16(uint32_t dst, const void* src, bool pred) {
    int sz = pred ? 16 : 0;
    asm volatile("cp.async.cg.shared.global [%0], [%1], 16, %2;\n"
                 :: "r"(dst), "l"(src), "r"(sz));
}

__global__ void __launch_bounds__(256) mma_gemm(int M, int N, int K,
                                                const __nv_bfloat16* __restrict__ Ah,
                                                const __nv_bfloat16* __restrict__ Al,
                                                const __nv_bfloat16* __restrict__ Bh,
                                                const __nv_bfloat16* __restrict__ Bl,
                                                const float* __restrict__ bias,
                                                float* __restrict__ C) {
    __shared__ __align__(16) char smem[2 * STG_BYTES];
    uint32_t sbase = (uint32_t)__cvta_generic_to_shared(smem);

    int bm = blockIdx.y * 128;
    int bn = blockIdx.x * 64;
    int tid = threadIdx.x;
    int warp = tid >> 5, lane = tid & 31;
    int wm = (warp & 3) * 32;       // warp M offset
    int wn = (warp >> 2) * 32;      // warp N offset (within 64-wide B tile)
    int g = lane >> 2;              // group id (0..7)
    int tg = lane & 3;              // thread in group

    float acc[2][4][4];
#pragma unroll
    for (int mt = 0; mt < 2; mt++)
#pragma unroll
        for (int nt = 0; nt < 4; nt++)
#pragma unroll
            for (int r = 0; r < 4; r++) acc[mt][nt][r] = 0.f;

    // loader indices (per thread): A chunks 512 (2 iters), B chunks 256 (1 iter)
    int aRow0 = tid >> 2;            // 0..63
    int aRow1 = aRow0 + 64;          // 64..127
    int kc = tid & 3;                // 16B chunk within 64B row
    int bRow = tid >> 2;             // 0..63

    int nTiles = K >> 5;             // K / 32

    // ---- prologue: load stage 0 ----
    {
        int kt = 0;
        uint32_t st = sbase;
        int r0 = bm + aRow0, r1 = bm + aRow1;
        bool v0 = r0 < M, v1 = r1 < M;
        int c0 = v0 ? r0 : 0, c1 = v1 ? r1 : 0;
        cp16(st + OFF_AH + swz(aRow0, kc), Ah + (size_t)c0 * K + kt + kc * 8, v0);
        cp16(st + OFF_AH + swz(aRow1, kc), Ah + (size_t)c1 * K + kt + kc * 8, v1);
        cp16(st + OFF_AL + swz(aRow0, kc), Al + (size_t)c0 * K + kt + kc * 8, v0);
        cp16(st + OFF_AL + swz(aRow1, kc), Al + (size_t)c1 * K + kt + kc * 8, v1);
        int br = bn + bRow;
        cp16(st + OFF_BH + swz(bRow, kc), Bh + (size_t)br * K + kt + kc * 8, true);
        cp16(st + OFF_BL + swz(bRow, kc), Bl + (size_t)br * K + kt + kc * 8, true);
        asm volatile("cp.async.commit_group;\n");
    }

    int lr = lane & 15, lc = lane >> 4;   // ldmatrix lane row / chunk-half

    for (int t = 0; t < nTiles; t++) {
        int buf = t & 1;
        if (t + 1 < nTiles) {
            int kt = (t + 1) << 5;
            uint32_t st = sbase + (buf ^ 1) * STG_BYTES;
            int r0 = bm + aRow0, r1 = bm + aRow1;
            bool v0 = r0 < M, v1 = r1 < M;
            int c0 = v0 ? r0 : 0, c1 = v1 ? r1 : 0;
            cp16(st + OFF_AH + swz(aRow0, kc), Ah + (size_t)c0 * K + kt + kc * 8, v0);
            cp16(st + OFF_AH + swz(aRow1, kc), Ah + (size_t)c1 * K + kt + kc * 8, v1);
            cp16(st + OFF_AL + swz(aRow0, kc), Al + (size_t)c0 * K + kt + kc * 8, v0);
            cp16(st + OFF_AL + swz(aRow1, kc), Al + (size_t)c1 * K + kt + kc * 8, v1);
            int br = bn + bRow;
            cp16(st + OFF_BH + swz(bRow, kc), Bh + (size_t)br * K + kt + kc * 8, true);
            cp16(st + OFF_BL + swz(bRow, kc), Bl + (size_t)br * K + kt + kc * 8, true);
            asm volatile("cp.async.commit_group;\n");
            asm volatile("cp.async.wait_group 1;\n");
        } else {
            asm volatile("cp.async.wait_group 0;\n");
        }
        __syncthreads();

        uint32_t st = sbase + buf * STG_BYTES;
#pragma unroll
        for (int kk = 0; kk < 2; kk++) {          // two k=16 slices
            int ch = kk * 2 + lc;                 // chunk for this lane
            uint32_t ah[2][4], al_[2][4], bh[2][4], bl[2][4];
#pragma unroll
            for (int mt = 0; mt < 2; mt++) {
                int row = wm + mt * 16 + lr;
                LDSM4(ah[mt],  st + OFF_AH + swz(row, ch));
                LDSM4(al_[mt], st + OFF_AL + swz(row, ch));
            }
#pragma unroll
            for (int pp = 0; pp < 2; pp++) {
                int row = wn + pp * 16 + lr;
                LDSM4(bh[pp], st + OFF_BH + swz(row, ch));
                LDSM4(bl[pp], st + OFF_BL + swz(row, ch));
            }
#pragma unroll
            for (int mt = 0; mt < 2; mt++)
#pragma unroll
                for (int pp = 0; pp < 2; pp++) {
                    MMA16816(acc[mt][pp * 2 + 0], ah[mt],  bh[pp][0], bh[pp][2]);
                    MMA16816(acc[mt][pp * 2 + 0], ah[mt],  bl[pp][0], bl[pp][2]);
                    MMA16816(acc[mt][pp * 2 + 0], al_[mt], bh[pp][0], bh[pp][2]);
                    MMA16816(acc[mt][pp * 2 + 1], ah[mt],  bh[pp][1], bh[pp][3]);
                    MMA16816(acc[mt][pp * 2 + 1], ah[mt],  bl[pp][1], bl[pp][3]);
                    MMA16816(acc[mt][pp * 2 + 1], al_[mt], bh[pp][1], bh[pp][3]);
                }
        }
        __syncthreads();
    }

    // epilogue
#pragma unroll
    for (int mt = 0; mt < 2; mt++) {
#pragma unroll
        for (int nt = 0; nt < 4; nt++) {
            int col = bn + wn + nt * 8 + 2 * tg;
            float bv0 = bias ? bias[col] : 0.f;
            float bv1 = bias ? bias[col + 1] : 0.f;
            int row0 = bm + wm + mt * 16 + g;
            if (row0 < M) {
                float2* p = (float2*)(C + (size_t)row0 * N + col);
                *p = make_float2(acc[mt][nt][0] + bv0, acc[mt][nt][1] + bv1);
            }
            int row1 = row0 + 8;
            if (row1 < M) {
                float2* p = (float2*)(C + (size_t)row1 * N + col);
                *p = make_float2(acc[mt][nt][2] + bv0, acc[mt][nt][3] + bv1);
            }
        }
    }
}

// ---------------- rmsnorm + rope + transpose for q/k/v ----------------
__global__ void __launch_bounds__(128) qkv_prep(const float* __restrict__ h,
                                                const float* __restrict__ pe,
                                                const float* __restrict__ qns,
                                                const float* __restrict__ kns,
                                                float* __restrict__ qn,
                                                float* __restrict__ qr,
                                                float* __restrict__ kr,
                                                float* __restrict__ vr) {
    int head = blockIdx.x;
    int l = blockIdx.y;
    int d = threadIdx.x;
    const float* base = h + (size_t)l * N1 + head * DH;
    float qv = base[d];
    float kv = base[HID + d];
    float vv = base[2 * HID + d];
    float qss = qv * qv, kss = kv * kv;
#pragma unroll
    for (int o = 16; o; o >>= 1) {
        qss += __shfl_xor_sync(0xffffffffu, qss, o);
        kss += __shfl_xor_sync(0xffffffffu, kss, o);
    }
    __shared__ float rq[4], rk[4];
    if ((d & 31) == 0) { rq[d >> 5] = qss; rk[d >> 5] = kss; }
    __syncthreads();
    float qt = rq[0] + rq[1] + rq[2] + rq[3];
    float kt = rk[0] + rk[1] + rk[2] + rk[3];
    float qnv = qv * rsqrtf(qt * (1.f / DH) + EPSV) * qns[d];
    float knv = kv * rsqrtf(kt * (1.f / DH) + EPSV) * kns[d];
    __shared__ float sq[DH], sk[DH];
    sq[d] = qnv; sk[d] = knv;
    __syncthreads();
    int p = d >> 1, r = d & 1;
    const float* per = pe + (((size_t)l * 64 + p) * 2 + r) * 2;
    float qro = per[0] * sq[2 * p] + per[1] * sq[2 * p + 1];
    float kro = per[0] * sk[2 * p] + per[1] * sk[2 * p + 1];
    size_t o = ((size_t)head * LQ + l) * DH + d;
    qn[o] = qnv; qr[o] = qro; kr[o] = kro; vr[o] = vv;
}

// ---------------- flash attention (fp32, online softmax) ----------------
__global__ void __launch_bounds__(256) flash_kernel(const float* __restrict__ Q,
                                                    const float* __restrict__ Kp,
                                                    const float* __restrict__ Vp,
                                                    int Lk,
                                                    long long kv_head_stride,
                                                    long long kv_row_stride,
                                                    float* __restrict__ Out,
                                                    int accumulate,
                                                    const float* __restrict__ scale_ptr) {
    __shared__ float Ks[32][128];
    __shared__ float Vs[32][128];
    int head = blockIdx.y;
    int qtile = blockIdx.x;
    int tid = threadIdx.x;
    int i = tid >> 2;
    int g = tid & 3;
    int l = qtile * 64 + i;
    const float sm_scale = 0.08838834764831845f;

    float q[32];
    const float* qrow = Q + ((size_t)head * LQ + l) * DH + g * 32;
#pragma unroll
    for (int c = 0; c < 32; c++) q[c] = qrow[c] * sm_scale;

    float m = -INFINITY, lsum = 0.f;
    float acc[32];
#pragma unroll
    for (int c = 0; c < 32; c++) acc[c] = 0.f;

    const float* Kh = Kp + head * kv_head_stride;
    const float* Vh = Vp + head * kv_head_stride;

    for (int kv0 = 0; kv0 < Lk; kv0 += 32) {
        for (int idx = tid; idx < 32 * 32; idx += 256) {
            int r = idx >> 5, c4 = (idx & 31) * 4;
            const float* krow = Kh + (size_t)(kv0 + r) * kv_row_stride;
            const float* vrow = Vh + (size_t)(kv0 + r) * kv_row_stride;
            *(float4*)&Ks[r][c4] = *(const float4*)(krow + c4);
            *(float4*)&Vs[r][c4] = *(const float4*)(vrow + c4);
        }
        __syncthreads();
        for (int j = 0; j < 32; j++) {
            float s = 0.f;
            const float* kr_ = &Ks[j][g * 32];
#pragma unroll
            for (int c = 0; c < 32; c++) s += q[c] * kr_[c];
            s += __shfl_xor_sync(0xffffffffu, s, 1);
            s += __shfl_xor_sync(0xffffffffu, s, 2);
            float mnew = fmaxf(m, s);
            if (mnew > m) {
                float f = __expf(m - mnew);
                lsum *= f;
#pragma unroll
                for (int c = 0; c < 32; c++) acc[c] *= f;
                m = mnew;
            }
            float p = __expf(s - m);
            lsum += p;
            const float* vr_ = &Vs[j][g * 32];
#pragma unroll
            for (int c = 0; c < 32; c++) acc[c] += p * vr_[c];
        }
        __syncthreads();
    }
    float inv = 1.f / lsum;
    float* orow = Out + (size_t)l * HID + head * DH + g * 32;
    if (accumulate) {
        float sc = *scale_ptr;
#pragma unroll
        for (int c = 0; c < 32; c++) orow[c] += sc * acc[c] * inv;
    } else {
#pragma unroll
        for (int c = 0; c < 32; c++) orow[c] = acc[c] * inv;
    }
}

// ---------------- fused = [attn_out, gelu(mlp)] -> bf16 hi/lo ----------------
__global__ void fuse_gelu(const float* __restrict__ attn,
                          const float* __restrict__ h,
                          __nv_bfloat16* __restrict__ fh,
                          __nv_bfloat16* __restrict__ fl) {
    size_t idx = (size_t)blockIdx.x * blockDim.x + threadIdx.x;
    if (idx >= (size_t)LQ * KF) return;
    int l = (int)(idx / KF);
    int j = (int)(idx % KF);
    float f;
    if (j < HID) {
        f = attn[(size_t)l * HID + j];
    } else {
        float v = h[(size_t)l * N1 + 3 * HID + (j - HID)];
        float v3 = v * v * v;
        f = 0.5f * v * (1.f + tanhf(0.7978845608028654f * (v + 0.044715f * v3)));
    }
    __nv_bfloat16 hh = __float2bfloat16(f);
    fh[idx] = hh;
    fl[idx] = __float2bfloat16(f - __bfloat162float(hh));
}

// ---------------- residual: out = x + gate * tmp ----------------
__global__ void final_kernel(const float* __restrict__ x,
                             const float* __restrict__ mod,
                             const float* __restrict__ tmp,
                             float* __restrict__ out) {
    size_t idx = (size_t)blockIdx.x * blockDim.x + threadIdx.x;
    if (idx >= (size_t)LQ * HID) return;
    int c = (int)(idx % HID);
    out[idx] = x[idx] + mod[2 * HID + c] * tmp[idx];
}

// ---------------- launch ----------------
extern "C" void kernel_launch(void* const* d_in, const int* in_sizes, int n_in,
                              void* d_out, int out_size) {
    const float* x          = (const float*)d_in[0];
    const float* vec        = (const float*)d_in[1];
    const float* pe         = (const float*)d_in[2];
    const float* image_proj = (const float*)d_in[3];
    const float* ip_scale   = (const float*)d_in[4];
    const float* mod_w      = (const float*)d_in[5];
    const float* mod_b      = (const float*)d_in[6];
    const float* w1         = (const float*)d_in[7];
    const float* b1         = (const float*)d_in[8];
    const float* w2         = (const float*)d_in[9];
    const float* b2         = (const float*)d_in[10];
    const float* qns        = (const float*)d_in[11];
    const float* kns        = (const float*)d_in[12];
    const float* ipkw       = (const float*)d_in[13];
    const float* ipvw       = (const float*)d_in[14];
    float* out = (float*)d_out;

    float *sv, *mod, *h, *qn, *qr, *kr, *vr, *attn, *ipk, *ipv, *tmp;
    __nv_bfloat16 *xmh, *xml, *w1h, *w1l, *w2h, *w2l, *fuh, *ful;
    __nv_bfloat16 *iph, *ipl, *ipkh, *ipkl, *ipvh, *ipvl;
    cudaGetSymbolAddress((void**)&sv, g_sv);
    cudaGetSymbolAddress((void**)&mod, g_mod);
    cudaGetSymbolAddress((void**)&h, g_h);
    cudaGetSymbolAddress((void**)&qn, g_qn);
    cudaGetSymbolAddress((void**)&qr, g_qr);
    cudaGetSymbolAddress((void**)&kr, g_kr);
    cudaGetSymbolAddress((void**)&vr, g_vr);
    cudaGetSymbolAddress((void**)&attn, g_attn);
    cudaGetSymbolAddress((void**)&ipk, g_ipk);
    cudaGetSymbolAddress((void**)&ipv, g_ipv);
    cudaGetSymbolAddress((void**)&tmp, g_tmp);
    cudaGetSymbolAddress((void**)&xmh, g_xmh);
    cudaGetSymbolAddress((void**)&xml, g_xml);
    cudaGetSymbolAddress((void**)&w1h, g_w1h);
    cudaGetSymbolAddress((void**)&w1l, g_w1l);
    cudaGetSymbolAddress((void**)&w2h, g_w2h);
    cudaGetSymbolAddress((void**)&w2l, g_w2l);
    cudaGetSymbolAddress((void**)&fuh, g_fuh);
    cudaGetSymbolAddress((void**)&ful, g_ful);
    cudaGetSymbolAddress((void**)&iph, g_iph);
    cudaGetSymbolAddress((void**)&ipl, g_ipl);
    cudaGetSymbolAddress((void**)&ipkh, g_ipkh);
    cudaGetSymbolAddress((void**)&ipkl, g_ipkl);
    cudaGetSymbolAddress((void**)&ipvh, g_ipvh);
    cudaGetSymbolAddress((void**)&ipvl, g_ipvl);

    silu_kernel<<<12, 256>>>(vec, sv);
    mod_gemv<<<3 * HID, 128>>>(sv, mod_w, mod_b, mod);
    ln_mod<<<LQ, 256>>>(x, mod, xmh, xml);

    // split weights / activations to bf16 hi+lo (vectorized, n % 4 == 0)
    {
        size_t n4;
        n4 = (size_t)N1 * HID / 4;
        split_bf16_v4<<<(unsigned)((n4 + 255) / 256), 256>>>((const float4*)w1, (__nv_bfloat162*)w1h, (__nv_bfloat162*)w1l, n4);
        n4 = (size_t)HID * KF / 4;
        split_bf16_v4<<<(unsigned)((n4 + 255) / 256), 256>>>((const float4*)w2, (__nv_bfloat162*)w2h, (__nv_bfloat162*)w2l, n4);
        n4 = (size_t)LIPN * CTX / 4;
        split_bf16_v4<<<(unsigned)((n4 + 255) / 256), 256>>>((const float4*)image_proj, (__nv_bfloat162*)iph, (__nv_bfloat162*)ipl, n4);
        n4 = (size_t)HID * CTX / 4;
        split_bf16_v4<<<(unsigned)((n4 + 255) / 256), 256>>>((const float4*)ipkw, (__nv_bfloat162*)ipkh, (__nv_bfloat162*)ipkl, n4);
        split_bf16_v4<<<(unsigned)((n4 + 255) / 256), 256>>>((const float4*)ipvw, (__nv_bfloat162*)ipvh, (__nv_bfloat162*)ipvl, n4);
    }

    // h = x_mod @ W1^T + b1 : (2048, 21504), K=3072
    mma_gemm<<<dim3(N1 / 64, LQ / 128), 256>>>(LQ, N1, HID, xmh, xml, w1h, w1l, b1, h);

    qkv_prep<<<dim3(NH, LQ), 128>>>(h, pe, qns, kns, qn, qr, kr, vr);

    // ip_k / ip_v : (64, 3072) = image_proj @ W^T, K=4096
    mma_gemm<<<dim3(HID / 64, 1), 256>>>(LIPN, HID, CTX, iph, ipl, ipkh, ipkl, nullptr, ipk);
    mma_gemm<<<dim3(HID / 64, 1), 256>>>(LIPN, HID, CTX, iph, ipl, ipvh, ipvl, nullptr, ipv);

    // self-attention (roped q/k)
    flash_kernel<<<dim3(LQ / 64, NH), 256>>>(qr, kr, vr, LQ,
                                             (long long)LQ * DH, (long long)DH,
                                             attn, 0, nullptr);
    // ip attention (un-roped q vs ip_k/ip_v), accumulates ip_scale * result
    flash_kernel<<<dim3(LQ / 64, NH), 256>>>(qn, ipk, ipv, LIPN,
                                             (long long)DH, (long long)HID,
                                             attn, 1, ip_scale);

    fuse_gelu<<<(LQ * KF + 255) / 256, 256>>>(attn, h, fuh, ful);

    // out_tmp = fused @ W2^T + b2 : (2048, 3072), K=15360
    mma_gemm<<<dim3(HID / 64, LQ / 128), 256>>>(LQ, HID, KF, fuh, ful, w2h, w2l, b2, tmp);

    final_kernel<<<(LQ * HID + 255) / 256, 256>>>(x, mod, tmp, out);
}

// round 14
// speedup vs baseline: 1.5675x; 1.0300x over previous
#include <cuda_runtime.h>
#include <cuda_bf16.h>
#include <cstdint>
#include <math.h>

#define HID  3072
#define LQ   2048
#define NH   24
#define DH   128
#define N1   21504      // 3*HID + MLP
#define MLPD 12288
#define KF   15360      // HID + MLP
#define LIPN 64
#define CTX  4096
#define EPSV 1e-6f

// ---------------- scratch (static device allocations) ----------------
__device__ float g_sv[HID];
__device__ float g_mod[3 * HID];
__device__ float g_h[LQ * N1];
__device__ float g_qn[NH * LQ * DH];
__device__ float g_qr[NH * LQ * DH];
__device__ float g_kr[NH * LQ * DH];
__device__ float g_vr[NH * LQ * DH];
__device__ float g_attn[LQ * HID];
__device__ float g_ipk[LIPN * HID];
__device__ float g_ipv[LIPN * HID];
__device__ float g_tmp[LQ * HID];
// K-split partial outputs for the small ip GEMMs (4 chunks each)
__device__ float g_ipkp[4 * LIPN * HID];
__device__ float g_ipvp[4 * LIPN * HID];

// bf16 split operands (hi / lo)
__device__ __nv_bfloat16 g_xmh[LQ * HID],   g_xml[LQ * HID];
__device__ __nv_bfloat16 g_w1h[N1 * HID],   g_w1l[N1 * HID];
__device__ __nv_bfloat16 g_w2h[HID * KF],   g_w2l[HID * KF];
__device__ __nv_bfloat16 g_fuh[LQ * KF],    g_ful[LQ * KF];
__device__ __nv_bfloat16 g_iph[LIPN * CTX], g_ipl[LIPN * CTX];
__device__ __nv_bfloat16 g_ipkh[HID * CTX], g_ipkl[HID * CTX];
__device__ __nv_bfloat16 g_ipvh[HID * CTX], g_ipvl[HID * CTX];

// ---------------- split fp32 -> bf16 hi + bf16 lo (vectorized) ----------------
__global__ void split_bf16_v4(const float4* __restrict__ src,
                              __nv_bfloat162* __restrict__ hi,
                              __nv_bfloat162* __restrict__ lo, size_t n4) {
    size_t i = (size_t)blockIdx.x * blockDim.x + threadIdx.x;
    if (i >= n4) return;
    float4 v = src[i];
    __nv_bfloat16 h0 = __float2bfloat16(v.x);
    __nv_bfloat16 h1 = __float2bfloat16(v.y);
    __nv_bfloat16 h2 = __float2bfloat16(v.z);
    __nv_bfloat16 h3 = __float2bfloat16(v.w);
    hi[2 * i]     = __nv_bfloat162(h0, h1);
    hi[2 * i + 1] = __nv_bfloat162(h2, h3);
    lo[2 * i]     = __nv_bfloat162(__float2bfloat16(v.x - __bfloat162float(h0)),
                                   __float2bfloat16(v.y - __bfloat162float(h1)));
    lo[2 * i + 1] = __nv_bfloat162(__float2bfloat16(v.z - __bfloat162float(h2)),
                                   __float2bfloat16(v.w - __bfloat162float(h3)));
}

// ---------------- small elementwise kernels ----------------
__global__ void silu_kernel(const float* __restrict__ v, float* __restrict__ sv) {
    int i = blockIdx.x * blockDim.x + threadIdx.x;
    if (i < HID) {
        float x = v[i];
        sv[i] = x / (1.f + __expf(-x));
    }
}

__global__ void __launch_bounds__(128) mod_gemv(const float* __restrict__ sv,
                                                const float* __restrict__ W,
                                                const float* __restrict__ b,
                                                float* __restrict__ mod) {
    int n = blockIdx.x;
    int tid = threadIdx.x;
    const float* w = W + (size_t)n * HID;
    float s = 0.f;
    for (int i = tid; i < HID; i += 128) s += sv[i] * w[i];
#pragma unroll
    for (int o = 16; o; o >>= 1) s += __shfl_xor_sync(0xffffffffu, s, o);
    __shared__ float red[4];
    if ((tid & 31) == 0) red[tid >> 5] = s;
    __syncthreads();
    if (tid == 0) mod[n] = red[0] + red[1] + red[2] + red[3] + b[n];
}

// layernorm + modulation, writes bf16 hi/lo directly (GEMM A operand)
__global__ void __launch_bounds__(256) ln_mod(const float* __restrict__ x,
                                              const float* __restrict__ mod,
                                              __nv_bfloat16* __restrict__ xh,
                                              __nv_bfloat16* __restrict__ xl) {
    int l = blockIdx.x;
    int tid = threadIdx.x;
    __shared__ float xs[HID];
    __shared__ float red1[8];
    __shared__ float red2[8];
    const float* xr = x + (size_t)l * HID;
    float s = 0.f;
    for (int i = tid; i < HID; i += 256) { float v = xr[i]; xs[i] = v; s += v; }
#pragma unroll
    for (int o = 16; o; o >>= 1) s += __shfl_xor_sync(0xffffffffu, s, o);
    if ((tid & 31) == 0) red1[tid >> 5] = s;
    __syncthreads();
    float tot = 0.f;
#pragma unroll
    for (int i = 0; i < 8; i++) tot += red1[i];
    float mu = tot * (1.f / HID);
    float s2 = 0.f;
    for (int i = tid; i < HID; i += 256) { float d = xs[i] - mu; s2 += d * d; }
#pragma unroll
    for (int o = 16; o; o >>= 1) s2 += __shfl_xor_sync(0xffffffffu, s2, o);
    if ((tid & 31) == 0) red2[tid >> 5] = s2;
    __syncthreads();
    float tot2 = 0.f;
#pragma unroll
    for (int i = 0; i < 8; i++) tot2 += red2[i];
    float rstd = rsqrtf(tot2 * (1.f / HID) + EPSV);
    for (int i = tid; i < HID; i += 256) {
        float nv = (xs[i] - mu) * rstd;
        float v = (1.f + mod[HID + i]) * nv + mod[i];
        __nv_bfloat16 h = __float2bfloat16(v);
        size_t o = (size_t)l * HID + i;
        xh[o] = h;
        xl[o] = __float2bfloat16(v - __bfloat162float(h));
    }
}

// ---------------- tensor-core GEMM (pipelined, dependency-spread) ----------------
// C = A @ B^T (+bias), bf16 split: Ah@Bh + Ah@Bl + Al@Bh, fp32 acc.
// 128x64x32 CTA tile, 8 warps (4x2 -> warp tile 32x32), 2-stage cp.async,
// ldmatrix.x4 fragments, XOR-swizzled smem. Split-term loop is OUTERMOST so
// consecutive MMAs never share an accumulator (HMMA RAW chains removed).
// kChunk > 0: K-split mode — blockIdx.z handles K range [z*kChunk, (z+1)*kChunk)
// and writes its partial sum to C + z*M*N.
#define MMA16816(d, a, b0, b1)                                               \
    asm volatile(                                                            \
        "mma.sync.aligned.m16n8k16.row.col.f32.bf16.bf16.f32 "               \
        "{%0,%1,%2,%3}, {%4,%5,%6,%7}, {%8,%9}, {%0,%1,%2,%3};"              \
        : "+f"(d[0]), "+f"(d[1]), "+f"(d[2]), "+f"(d[3])                     \
        : "r"(a[0]), "r"(a[1]), "r"(a[2]), "r"(a[3]), "r"(b0), "r"(b1))

#define LDSM4(R, addr)                                                       \
    asm volatile("ldmatrix.sync.aligned.m8n8.x4.shared.b16 {%0,%1,%2,%3}, [%4];" \
        : "=r"((R)[0]), "=r"((R)[1]), "=r"((R)[2]), "=r"((R)[3]) : "r"(addr))

// per-stage byte offsets: Ah 0, Al 8192, Bh 16384, Bl 20480; stage stride 24576
#define STG_BYTES 24576
#define OFF_AH 0
#define OFF_AL 8192
#define OFF_BH 16384
#define OFF_BL 20480

// row = tile row, chunk = 16B column chunk (k/8). 64B rows, XOR swizzle.
__device__ __forceinline__ uint32_t swz(int row, int chunk) {
    return (uint32_t)(row * 64 + ((chunk ^ ((row >> 1) & 3)) << 4));
}

__device__ __forceinline__ void cp16(uint32_t dst, const void* src, bool pred) {
    int sz = pred ? 16 : 0;
    asm volatile("cp.async.cg.shared.global [%0], [%1], 16, %2;\n"
                 :: "r"(dst), "l"(src), "r"(sz));
}

__global__ void __launch_bounds__(256) mma_gemm(int M, int N, int K, int kChunk,
                                                const __nv_bfloat16* __restrict__ Ah,
                                                const __nv_bfloat16* __restrict__ Al,
                                                const __nv_bfloat16* __restrict__ Bh,
                                                const __nv_bfloat16* __restrict__ Bl,
                                                const float* __restrict__ bias,
                                                float* __restrict__ C) {
    __shared__ __align__(16) char smem[2 * STG_BYTES];
    uint32_t sbase = (uint32_t)__cvta_generic_to_shared(smem);

    int bm = blockIdx.y * 128;
    int bn = blockIdx.x * 64;
    int tid = threadIdx.x;
    int warp = tid >> 5, lane = tid & 31;
    int wm = (warp & 3) * 32;       // warp M offset
    int wn = (warp >> 2) * 32;      // warp N offset (within 64-wide B tile)
    int g = lane >> 2;              // group id (0..7)
    int tg = lane & 3;              // thread in group

    int kBeg = 0, kLen = K;
    if (kChunk > 0) {
        kBeg = blockIdx.z * kChunk;
        kLen = kChunk;
        C += (size_t)blockIdx.z * M * N;
    }

    float acc[2][4][4];
#pragma unroll
    for (int mt = 0; mt < 2; mt++)
#pragma unroll
        for (int nt = 0; nt < 4; nt++)
#pragma unroll
            for (int r = 0; r < 4; r++) acc[mt][nt][r] = 0.f;

    // loader indices (per thread)
    int aRow0 = tid >> 2;            // 0..63
    int aRow1 = aRow0 + 64;          // 64..127
    int kc = tid & 3;                // 16B chunk within 64B row
    int bRow = tid >> 2;             // 0..63

    int nTiles = kLen >> 5;          // kLen / 32

    // ---- prologue: load stage 0 ----
    {
        int kt = kBeg;
        uint32_t st = sbase;
        int r0 = bm + aRow0, r1 = bm + aRow1;
        bool v0 = r0 < M, v1 = r1 < M;
        int c0 = v0 ? r0 : 0, c1 = v1 ? r1 : 0;
        cp16(st + OFF_AH + swz(aRow0, kc), Ah + (size_t)c0 * K + kt + kc * 8, v0);
        cp16(st + OFF_AH + swz(aRow1, kc), Ah + (size_t)c1 * K + kt + kc * 8, v1);
        cp16(st + OFF_AL + swz(aRow0, kc), Al + (size_t)c0 * K + kt + kc * 8, v0);
        cp16(st + OFF_AL + swz(aRow1, kc), Al + (size_t)c1 * K + kt + kc * 8, v1);
        int br = bn + bRow;
        cp16(st + OFF_BH + swz(bRow, kc), Bh + (size_t)br * K + kt + kc * 8, true);
        cp16(st + OFF_BL + swz(bRow, kc), Bl + (size_t)br * K + kt + kc * 8, true);
        asm volatile("cp.async.commit_group;\n");
    }

    int lr = lane & 15, lc = lane >> 4;   // ldmatrix lane row / chunk-half

    for (int t = 0; t < nTiles; t++) {
        int buf = t & 1;
        if (t + 1 < nTiles) {
            int kt = kBeg + ((t + 1) << 5);
            uint32_t st = sbase + (buf ^ 1) * STG_BYTES;
            int r0 = bm + aRow0, r1 = bm + aRow1;
            bool v0 = r0 < M, v1 = r1 < M;
            int c0 = v0 ? r0 : 0, c1 = v1 ? r1 : 0;
            cp16(st + OFF_AH + swz(aRow0, kc), Ah + (size_t)c0 * K + kt + kc * 8, v0);
            cp16(st + OFF_AH + swz(aRow1, kc), Ah + (size_t)c1 * K + kt + kc * 8, v1);
            cp16(st + OFF_AL + swz(aRow0, kc), Al + (size_t)c0 * K + kt + kc * 8, v0);
            cp16(st + OFF_AL + swz(aRow1, kc), Al + (size_t)c1 * K + kt + kc * 8, v1);
            int br = bn + bRow;
            cp16(st + OFF_BH + swz(bRow, kc), Bh + (size_t)br * K + kt + kc * 8, true);
            cp16(st + OFF_BL + swz(bRow, kc), Bl + (size_t)br * K + kt + kc * 8, true);
            asm volatile("cp.async.commit_group;\n");
            asm volatile("cp.async.wait_group 1;\n");
        } else {
            asm volatile("cp.async.wait_group 0;\n");
        }
        __syncthreads();

        uint32_t st = sbase + buf * STG_BYTES;
#pragma unroll
        for (int kk = 0; kk < 2; kk++) {          // two k=16 slices
            int ch = kk * 2 + lc;                 // chunk for this lane
            uint32_t ah[2][4], al_[2][4], bh[2][4], bl[2][4];
#pragma unroll
            for (int mt = 0; mt < 2; mt++) {
                int row = wm + mt * 16 + lr;
                LDSM4(ah[mt],  st + OFF_AH + swz(row, ch));
                LDSM4(al_[mt], st + OFF_AL + swz(row, ch));
            }
#pragma unroll
            for (int pp = 0; pp < 2; pp++) {
                int row = wn + pp * 16 + lr;
                LDSM4(bh[pp], st + OFF_BH + swz(row, ch));
                LDSM4(bl[pp], st + OFF_BL + swz(row, ch));
            }
            // split-term outermost: no two consecutive MMAs share an accumulator
            // term Ah x Bh
#pragma unroll
            for (int mt = 0; mt < 2; mt++)
#pragma unroll
                for (int pp = 0; pp < 2; pp++) {
                    MMA16816(acc[mt][pp * 2 + 0], ah[mt], bh[pp][0], bh[pp][2]);
                    MMA16816(acc[mt][pp * 2 + 1], ah[mt], bh[pp][1], bh[pp][3]);
                }
            // term Ah x Bl
#pragma unroll
            for (int mt = 0; mt < 2; mt++)
#pragma unroll
                for (int pp = 0; pp < 2; pp++) {
                    MMA16816(acc[mt][pp * 2 + 0], ah[mt], bl[pp][0], bl[pp][2]);
                    MMA16816(acc[mt][pp * 2 + 1], ah[mt], bl[pp][1], bl[pp][3]);
                }
            // term Al x Bh
#pragma unroll
            for (int mt = 0; mt < 2; mt++)
#pragma unroll
                for (int pp = 0; pp < 2; pp++) {
                    MMA16816(acc[mt][pp * 2 + 0], al_[mt], bh[pp][0], bh[pp][2]);
                    MMA16816(acc[mt][pp * 2 + 1], al_[mt], bh[pp][1], bh[pp][3]);
                }
        }
        __syncthreads();
    }

    // epilogue
#pragma unroll
    for (int mt = 0; mt < 2; mt++) {
#pragma unroll
        for (int nt = 0; nt < 4; nt++) {
            int col = bn + wn + nt * 8 + 2 * tg;
            float bv0 = bias ? bias[col] : 0.f;
            float bv1 = bias ? bias[col + 1] : 0.f;
            int row0 = bm + wm + mt * 16 + g;
            if (row0 < M) {
                float2* p = (float2*)(C + (size_t)row0 * N + col);
                *p = make_float2(acc[mt][nt][0] + bv0, acc[mt][nt][1] + bv1);
            }
            int row1 = row0 + 8;
            if (row1 < M) {
                float2* p = (float2*)(C + (size_t)row1 * N + col);
                *p = make_float2(acc[mt][nt][2] + bv0, acc[mt][nt][3] + bv1);
            }
        }
    }
}

// ---------------- fixed-order reduction of 4 K-split partials ----------------
__global__ void reduce4(const float* __restrict__ p, float* __restrict__ out, int n) {
    int i = blockIdx.x * blockDim.x + threadIdx.x;
    if (i >= n) return;
    out[i] = ((p[i] + p[n + i]) + p[2 * n + i]) + p[3 * n + i];
}

// ---------------- rmsnorm + rope + transpose for q/k/v ----------------
__global__ void __launch_bounds__(128) qkv_prep(const float* __restrict__ h,
                                                const float* __restrict__ pe,
                                                const float* __restrict__ qns,
                                                const float* __restrict__ kns,
                                                float* __restrict__ qn,
                                                float* __restrict__ qr,
                                                float* __restrict__ kr,
                                                float* __restrict__ vr) {
    int head = blockIdx.x;
    int l = blockIdx.y;
    int d = threadIdx.x;
    const float* base = h + (size_t)l * N1 + head * DH;
    float qv = base[d];
    float kv = base[HID + d];
    float vv = base[2 * HID + d];
    float qss = qv * qv, kss = kv * kv;
#pragma unroll
    for (int o = 16; o; o >>= 1) {
        qss += __shfl_xor_sync(0xffffffffu, qss, o);
        kss += __shfl_xor_sync(0xffffffffu, kss, o);
    }
    __shared__ float rq[4], rk[4];
    if ((d & 31) == 0) { rq[d >> 5] = qss; rk[d >> 5] = kss; }
    __syncthreads();
    float qt = rq[0] + rq[1] + rq[2] + rq[3];
    float kt = rk[0] + rk[1] + rk[2] + rk[3];
    float qnv = qv * rsqrtf(qt * (1.f / DH) + EPSV) * qns[d];
    float knv = kv * rsqrtf(kt * (1.f / DH) + EPSV) * kns[d];
    __shared__ float sq[DH], sk[DH];
    sq[d] = qnv; sk[d] = knv;
    __syncthreads();
    int p = d >> 1, r = d & 1;
    const float* per = pe + (((size_t)l * 64 + p) * 2 + r) * 2;
    float qro = per[0] * sq[2 * p] + per[1] * sq[2 * p + 1];
    float kro = per[0] * sk[2 * p] + per[1] * sk[2 * p + 1];
    size_t o = ((size_t)head * LQ + l) * DH + d;
    qn[o] = qnv; qr[o] = qro; kr[o] = kro; vr[o] = vv;
}

// ---------------- flash attention (fp32, online softmax) ----------------
__global__ void __launch_bounds__(256) flash_kernel(const float* __restrict__ Q,
                                                    const float* __restrict__ Kp,
                                                    const float* __restrict__ Vp,
                                                    int Lk,
                                                    long long kv_head_stride,
                                                    long long kv_row_stride,
                                                    float* __restrict__ Out,
                                                    int accumulate,
                                                    const float* __restrict__ scale_ptr) {
    __shared__ float Ks[32][128];
    __shared__ float Vs[32][128];
    int head = blockIdx.y;
    int qtile = blockIdx.x;
    int tid = threadIdx.x;
    int i = tid >> 2;
    int g = tid & 3;
    int l = qtile * 64 + i;
    const float sm_scale = 0.08838834764831845f;

    float q[32];
    const float* qrow = Q + ((size_t)head * LQ + l) * DH + g * 32;
#pragma unroll
    for (int c = 0; c < 32; c++) q[c] = qrow[c] * sm_scale;

    float m = -INFINITY, lsum = 0.f;
    float acc[32];
#pragma unroll
    for (int c = 0; c < 32; c++) acc[c] = 0.f;

    const float* Kh = Kp + head * kv_head_stride;
    const float* Vh = Vp + head * kv_head_stride;

    for (int kv0 = 0; kv0 < Lk; kv0 += 32) {
        for (int idx = tid; idx < 32 * 32; idx += 256) {
            int r = idx >> 5, c4 = (idx & 31) * 4;
            const float* krow = Kh + (size_t)(kv0 + r) * kv_row_stride;
            const float* vrow = Vh + (size_t)(kv0 + r) * kv_row_stride;
            *(float4*)&Ks[r][c4] = *(const float4*)(krow + c4);
            *(float4*)&Vs[r][c4] = *(const float4*)(vrow + c4);
        }
        __syncthreads();
        for (int j = 0; j < 32; j++) {
            float s = 0.f;
            const float* kr_ = &Ks[j][g * 32];
#pragma unroll
            for (int c = 0; c < 32; c++) s += q[c] * kr_[c];
            s += __shfl_xor_sync(0xffffffffu, s, 1);
            s += __shfl_xor_sync(0xffffffffu, s, 2);
            float mnew = fmaxf(m, s);
            if (mnew > m) {
                float f = __expf(m - mnew);
                lsum *= f;
#pragma unroll
                for (int c = 0; c < 32; c++) acc[c] *= f;
                m = mnew;
            }
            float p = __expf(s - m);
            lsum += p;
            const float* vr_ = &Vs[j][g * 32];
#pragma unroll
            for (int c = 0; c < 32; c++) acc[c] += p * vr_[c];
        }
        __syncthreads();
    }
    float inv = 1.f / lsum;
    float* orow = Out + (size_t)l * HID + head * DH + g * 32;
    if (accumulate) {
        float sc = *scale_ptr;
#pragma unroll
        for (int c = 0; c < 32; c++) orow[c] += sc * acc[c] * inv;
    } else {
#pragma unroll
        for (int c = 0; c < 32; c++) orow[c] = acc[c] * inv;
    }
}

// ---------------- fused = [attn_out, gelu(mlp)] -> bf16 hi/lo ----------------
__global__ void fuse_gelu(const float* __restrict__ attn,
                          const float* __restrict__ h,
                          __nv_bfloat16* __restrict__ fh,
                          __nv_bfloat16* __restrict__ fl) {
    size_t idx = (size_t)blockIdx.x * blockDim.x + threadIdx.x;
    if (idx >= (size_t)LQ * KF) return;
    int l = (int)(idx / KF);
    int j = (int)(idx % KF);
    float f;
    if (j < HID) {
        f = attn[(size_t)l * HID + j];
    } else {
        float v = h[(size_t)l * N1 + 3 * HID + (j - HID)];
        float v3 = v * v * v;
        f = 0.5f * v * (1.f + tanhf(0.7978845608028654f * (v + 0.044715f * v3)));
    }
    __nv_bfloat16 hh = __float2bfloat16(f);
    fh[idx] = hh;
    fl[idx] = __float2bfloat16(f - __bfloat162float(hh));
}

// ---------------- residual: out = x + gate * tmp ----------------
__global__ void final_kernel(const float* __restrict__ x,
                             const float* __restrict__ mod,
                             const float* __restrict__ tmp,
                             float* __restrict__ out) {
    size_t idx = (size_t)blockIdx.x * blockDim.x + threadIdx.x;
    if (idx >= (size_t)LQ * HID) return;
    int c = (int)(idx % HID);
    out[idx] = x[idx] + mod[2 * HID + c] * tmp[idx];
}

// ---------------- launch ----------------
extern "C" void kernel_launch(void* const* d_in, const int* in_sizes, int n_in,
                              void* d_out, int out_size) {
    const float* x          = (const float*)d_in[0];
    const float* vec        = (const float*)d_in[1];
    const float* pe         = (const float*)d_in[2];
    const float* image_proj = (const float*)d_in[3];
    const float* ip_scale   = (const float*)d_in[4];
    const float* mod_w      = (const float*)d_in[5];
    const float* mod_b      = (const float*)d_in[6];
    const float* w1         = (const float*)d_in[7];
    const float* b1         = (const float*)d_in[8];
    const float* w2         = (const float*)d_in[9];
    const float* b2         = (const float*)d_in[10];
    const float* qns        = (const float*)d_in[11];
    const float* kns        = (const float*)d_in[12];
    const float* ipkw       = (const float*)d_in[13];
    const float* ipvw       = (const float*)d_in[14];
    float* out = (float*)d_out;

    float *sv, *mod, *h, *qn, *qr, *kr, *vr, *attn, *ipk, *ipv, *tmp, *ipkp, *ipvp;
    __nv_bfloat16 *xmh, *xml, *w1h, *w1l, *w2h, *w2l, *fuh, *ful;
    __nv_bfloat16 *iph, *ipl, *ipkh, *ipkl, *ipvh, *ipvl;
    cudaGetSymbolAddress((void**)&sv, g_sv);
    cudaGetSymbolAddress((void**)&mod, g_mod);
    cudaGetSymbolAddress((void**)&h, g_h);
    cudaGetSymbolAddress((void**)&qn, g_qn);
    cudaGetSymbolAddress((void**)&qr, g_qr);
    cudaGetSymbolAddress((void**)&kr, g_kr);
    cudaGetSymbolAddress((void**)&vr, g_vr);
    cudaGetSymbolAddress((void**)&attn, g_attn);
    cudaGetSymbolAddress((void**)&ipk, g_ipk);
    cudaGetSymbolAddress((void**)&ipv, g_ipv);
    cudaGetSymbolAddress((void**)&tmp, g_tmp);
    cudaGetSymbolAddress((void**)&ipkp, g_ipkp);
    cudaGetSymbolAddress((void**)&ipvp, g_ipvp);
    cudaGetSymbolAddress((void**)&xmh, g_xmh);
    cudaGetSymbolAddress((void**)&xml, g_xml);
    cudaGetSymbolAddress((void**)&w1h, g_w1h);
    cudaGetSymbolAddress((void**)&w1l, g_w1l);
    cudaGetSymbolAddress((void**)&w2h, g_w2h);
    cudaGetSymbolAddress((void**)&w2l, g_w2l);
    cudaGetSymbolAddress((void**)&fuh, g_fuh);
    cudaGetSymbolAddress((void**)&ful, g_ful);
    cudaGetSymbolAddress((void**)&iph, g_iph);
    cudaGetSymbolAddress((void**)&ipl, g_ipl);
    cudaGetSymbolAddress((void**)&ipkh, g_ipkh);
    cudaGetSymbolAddress((void**)&ipkl, g_ipkl);
    cudaGetSymbolAddress((void**)&ipvh, g_ipvh);
    cudaGetSymbolAddress((void**)&ipvl, g_ipvl);

    silu_kernel<<<12, 256>>>(vec, sv);
    mod_gemv<<<3 * HID, 128>>>(sv, mod_w, mod_b, mod);
    ln_mod<<<LQ, 256>>>(x, mod, xmh, xml);

    // split weights / activations to bf16 hi+lo (vectorized, n % 4 == 0)
    {
        size_t n4;
        n4 = (size_t)N1 * HID / 4;
        split_bf16_v4<<<(unsigned)((n4 + 255) / 256), 256>>>((const float4*)w1, (__nv_bfloat162*)w1h, (__nv_bfloat162*)w1l, n4);
        n4 = (size_t)HID * KF / 4;
        split_bf16_v4<<<(unsigned)((n4 + 255) / 256), 256>>>((const float4*)w2, (__nv_bfloat162*)w2h, (__nv_bfloat162*)w2l, n4);
        n4 = (size_t)LIPN * CTX / 4;
        split_bf16_v4<<<(unsigned)((n4 + 255) / 256), 256>>>((const float4*)image_proj, (__nv_bfloat162*)iph, (__nv_bfloat162*)ipl, n4);
        n4 = (size_t)HID * CTX / 4;
        split_bf16_v4<<<(unsigned)((n4 + 255) / 256), 256>>>((const float4*)ipkw, (__nv_bfloat162*)ipkh, (__nv_bfloat162*)ipkl, n4);
        split_bf16_v4<<<(unsigned)((n4 + 255) / 256), 256>>>((const float4*)ipvw, (__nv_bfloat162*)ipvh, (__nv_bfloat162*)ipvl, n4);
    }

    // h = x_mod @ W1^T + b1 : (2048, 21504), K=3072
    mma_gemm<<<dim3(N1 / 64, LQ / 128), 256>>>(LQ, N1, HID, 0, xmh, xml, w1h, w1l, b1, h);

    qkv_prep<<<dim3(NH, LQ), 128>>>(h, pe, qns, kns, qn, qr, kr, vr);

    // ip_k / ip_v : (64, 3072) = image_proj @ W^T, K=4096 — K-split x4 for occupancy
    mma_gemm<<<dim3(HID / 64, 1, 4), 256>>>(LIPN, HID, CTX, CTX / 4, iph, ipl, ipkh, ipkl, nullptr, ipkp);
    mma_gemm<<<dim3(HID / 64, 1, 4), 256>>>(LIPN, HID, CTX, CTX / 4, iph, ipl, ipvh, ipvl, nullptr, ipvp);
    reduce4<<<(LIPN * HID + 255) / 256, 256>>>(ipkp, ipk, LIPN * HID);
    reduce4<<<(LIPN * HID + 255) / 256, 256>>>(ipvp, ipv, LIPN * HID);

    // self-attention (roped q/k)
    flash_kernel<<<dim3(LQ / 64, NH), 256>>>(qr, kr, vr, LQ,
                                             (long long)LQ * DH, (long long)DH,
                                             attn, 0, nullptr);
    // ip attention (un-roped q vs ip_k/ip_v), accumulates ip_scale * result
    flash_kernel<<<dim3(LQ / 64, NH), 256>>>(qn, ipk, ipv, LIPN,
                                             (long long)DH, (long long)HID,
                                             attn, 1, ip_scale);

    fuse_gelu<<<(LQ * KF + 255) / 256, 256>>>(attn, h, fuh, ful);

    // out_tmp = fused @ W2^T + b2 : (2048, 3072), K=15360
    mma_gemm<<<dim3(HID / 64, LQ / 128), 256>>>(LQ, HID, KF, 0, fuh, ful, w2h, w2l, b2, tmp);

    final_kernel<<<(LQ * HID + 255) / 256, 256>>>(x, mod, tmp, out);
}

// round 15
// speedup vs baseline: 1.5741x; 1.0043x over previous
#include <cuda_runtime.h>
#include <cuda_bf16.h>
#include <cstdint>
#include <math.h>

#define HID  3072
#define LQ   2048
#define NH   24
#define DH   128
#define N1   21504      // 3*HID + MLP
#define MLPD 12288
#define KF   15360      // HID + MLP
#define LIPN 64
#define CTX  4096
#define EPSV 1e-6f

// ---------------- scratch (static device allocations) ----------------
__device__ float g_mod[3 * HID];
__device__ float g_h[LQ * N1];
__device__ float g_qn[NH * LQ * DH];
__device__ float g_qr[NH * LQ * DH];
__device__ float g_kr[NH * LQ * DH];
__device__ float g_vr[NH * LQ * DH];
__device__ float g_attn[LQ * HID];
__device__ float g_ipk[LIPN * HID];
__device__ float g_ipv[LIPN * HID];
__device__ float g_tmp[LQ * HID];
// K-split partial outputs for the small ip GEMMs (4 chunks each)
__device__ float g_ipkp[4 * LIPN * HID];
__device__ float g_ipvp[4 * LIPN * HID];

// bf16 split operands (hi / lo)
__device__ __nv_bfloat16 g_xmh[LQ * HID],   g_xml[LQ * HID];
__device__ __nv_bfloat16 g_w1h[N1 * HID],   g_w1l[N1 * HID];
__device__ __nv_bfloat16 g_w2h[HID * KF],   g_w2l[HID * KF];
__device__ __nv_bfloat16 g_fuh[LQ * KF],    g_ful[LQ * KF];
__device__ __nv_bfloat16 g_iph[LIPN * CTX], g_ipl[LIPN * CTX];
__device__ __nv_bfloat16 g_ipkh[HID * CTX], g_ipkl[HID * CTX];
__device__ __nv_bfloat16 g_ipvh[HID * CTX], g_ipvl[HID * CTX];

// ---------------- split fp32 -> bf16 hi + bf16 lo (vectorized) ----------------
__global__ void split_bf16_v4(const float4* __restrict__ src,
                              __nv_bfloat162* __restrict__ hi,
                              __nv_bfloat162* __restrict__ lo, size_t n4) {
    size_t i = (size_t)blockIdx.x * blockDim.x + threadIdx.x;
    if (i >= n4) return;
    float4 v = src[i];
    __nv_bfloat16 h0 = __float2bfloat16(v.x);
    __nv_bfloat16 h1 = __float2bfloat16(v.y);
    __nv_bfloat16 h2 = __float2bfloat16(v.z);
    __nv_bfloat16 h3 = __float2bfloat16(v.w);
    hi[2 * i]     = __nv_bfloat162(h0, h1);
    hi[2 * i + 1] = __nv_bfloat162(h2, h3);
    lo[2 * i]     = __nv_bfloat162(__float2bfloat16(v.x - __bfloat162float(h0)),
                                   __float2bfloat16(v.y - __bfloat162float(h1)));
    lo[2 * i + 1] = __nv_bfloat162(__float2bfloat16(v.z - __bfloat162float(h2)),
                                   __float2bfloat16(v.w - __bfloat162float(h3)));
}

// ---------------- fused silu + gemv: mod = silu(vec) @ W^T + b ----------------
__global__ void __launch_bounds__(128) mod_gemv(const float* __restrict__ vec,
                                                const float* __restrict__ W,
                                                const float* __restrict__ b,
                                                float* __restrict__ mod) {
    int n = blockIdx.x;
    int tid = threadIdx.x;
    const float* w = W + (size_t)n * HID;
    float s = 0.f;
    for (int i = tid; i < HID; i += 128) {
        float v = vec[i];
        s += (v / (1.f + __expf(-v))) * w[i];
    }
#pragma unroll
    for (int o = 16; o; o >>= 1) s += __shfl_xor_sync(0xffffffffu, s, o);
    __shared__ float red[4];
    if ((tid & 31) == 0) red[tid >> 5] = s;
    __syncthreads();
    if (tid == 0) mod[n] = red[0] + red[1] + red[2] + red[3] + b[n];
}

// layernorm + modulation, writes bf16 hi/lo directly (GEMM A operand)
__global__ void __launch_bounds__(256) ln_mod(const float* __restrict__ x,
                                              const float* __restrict__ mod,
                                              __nv_bfloat16* __restrict__ xh,
                                              __nv_bfloat16* __restrict__ xl) {
    int l = blockIdx.x;
    int tid = threadIdx.x;
    __shared__ float xs[HID];
    __shared__ float red1[8];
    __shared__ float red2[8];
    const float* xr = x + (size_t)l * HID;
    float s = 0.f;
    for (int i = tid; i < HID; i += 256) { float v = xr[i]; xs[i] = v; s += v; }
#pragma unroll
    for (int o = 16; o; o >>= 1) s += __shfl_xor_sync(0xffffffffu, s, o);
    if ((tid & 31) == 0) red1[tid >> 5] = s;
    __syncthreads();
    float tot = 0.f;
#pragma unroll
    for (int i = 0; i < 8; i++) tot += red1[i];
    float mu = tot * (1.f / HID);
    float s2 = 0.f;
    for (int i = tid; i < HID; i += 256) { float d = xs[i] - mu; s2 += d * d; }
#pragma unroll
    for (int o = 16; o; o >>= 1) s2 += __shfl_xor_sync(0xffffffffu, s2, o);
    if ((tid & 31) == 0) red2[tid >> 5] = s2;
    __syncthreads();
    float tot2 = 0.f;
#pragma unroll
    for (int i = 0; i < 8; i++) tot2 += red2[i];
    float rstd = rsqrtf(tot2 * (1.f / HID) + EPSV);
    for (int i = tid; i < HID; i += 256) {
        float nv = (xs[i] - mu) * rstd;
        float v = (1.f + mod[HID + i]) * nv + mod[i];
        __nv_bfloat16 h = __float2bfloat16(v);
        size_t o = (size_t)l * HID + i;
        xh[o] = h;
        xl[o] = __float2bfloat16(v - __bfloat162float(h));
    }
}

// ---------------- tensor-core GEMM (pipelined, dependency-spread) ----------------
// C = A @ B^T (+bias), bf16 split: Ah@Bh + Ah@Bl + Al@Bh, fp32 acc.
// 128x64x32 CTA tile, 8 warps (4x2 -> warp tile 32x32), 2-stage cp.async,
// ldmatrix.x4 fragments, XOR-swizzled smem.
// GRID MAPPING: blockIdx.x = M tile, blockIdx.y = N tile — a wave spans all
// M tiles of few N slabs, so B slabs are L2-served (read once from DRAM).
// kChunk > 0: K-split mode — blockIdx.z handles K range [z*kChunk, (z+1)*kChunk)
// and writes its partial sum to C + z*M*N.
#define MMA16816(d, a, b0, b1)                                               \
    asm volatile(                                                            \
        "mma.sync.aligned.m16n8k16.row.col.f32.bf16.bf16.f32 "               \
        "{%0,%1,%2,%3}, {%4,%5,%6,%7}, {%8,%9}, {%0,%1,%2,%3};"              \
        : "+f"(d[0]), "+f"(d[1]), "+f"(d[2]), "+f"(d[3])                     \
        : "r"(a[0]), "r"(a[1]), "r"(a[2]), "r"(a[3]), "r"(b0), "r"(b1))

#define LDSM4(R, addr)                                                       \
    asm volatile("ldmatrix.sync.aligned.m8n8.x4.shared.b16 {%0,%1,%2,%3}, [%4];" \
        : "=r"((R)[0]), "=r"((R)[1]), "=r"((R)[2]), "=r"((R)[3]) : "r"(addr))

// per-stage byte offsets: Ah 0, Al 8192, Bh 16384, Bl 20480; stage stride 24576
#define STG_BYTES 24576
#define OFF_AH 0
#define OFF_AL 8192
#define OFF_BH 16384
#define OFF_BL 20480

// row = tile row, chunk = 16B column chunk (k/8). 64B rows, XOR swizzle.
__device__ __forceinline__ uint32_t swz(int row, int chunk) {
    return (uint32_t)(row * 64 + ((chunk ^ ((row >> 1) & 3)) << 4));
}

__device__ __forceinline__ void cp16(uint32_t dst, const void* src, bool pred) {
    int sz = pred ? 16 : 0;
    asm volatile("cp.async.cg.shared.global [%0], [%1], 16, %2;\n"
                 :: "r"(dst), "l"(src), "r"(sz));
}

__global__ void __launch_bounds__(256) mma_gemm(int M, int N, int K, int kChunk,
                                                const __nv_bfloat16* __restrict__ Ah,
                                                const __nv_bfloat16* __restrict__ Al,
                                                const __nv_bfloat16* __restrict__ Bh,
                                                const __nv_bfloat16* __restrict__ Bl,
                                                const float* __restrict__ bias,
                                                float* __restrict__ C) {
    __shared__ __align__(16) char smem[2 * STG_BYTES];
    uint32_t sbase = (uint32_t)__cvta_generic_to_shared(smem);

    int bm = blockIdx.x * 128;      // M on x (fast dim) -> wave shares B slabs
    int bn = blockIdx.y * 64;
    int tid = threadIdx.x;
    int warp = tid >> 5, lane = tid & 31;
    int wm = (warp & 3) * 32;       // warp M offset
    int wn = (warp >> 2) * 32;      // warp N offset (within 64-wide B tile)
    int g = lane >> 2;              // group id (0..7)
    int tg = lane & 3;              // thread in group

    int kBeg = 0, kLen = K;
    if (kChunk > 0) {
        kBeg = blockIdx.z * kChunk;
        kLen = kChunk;
        C += (size_t)blockIdx.z * M * N;
    }

    float acc[2][4][4];
#pragma unroll
    for (int mt = 0; mt < 2; mt++)
#pragma unroll
        for (int nt = 0; nt < 4; nt++)
#pragma unroll
            for (int r = 0; r < 4; r++) acc[mt][nt][r] = 0.f;

    // loader indices (per thread)
    int aRow0 = tid >> 2;            // 0..63
    int aRow1 = aRow0 + 64;          // 64..127
    int kc = tid & 3;                // 16B chunk within 64B row
    int bRow = tid >> 2;             // 0..63

    int nTiles = kLen >> 5;          // kLen / 32

    // ---- prologue: load stage 0 ----
    {
        int kt = kBeg;
        uint32_t st = sbase;
        int r0 = bm + aRow0, r1 = bm + aRow1;
        bool v0 = r0 < M, v1 = r1 < M;
        int c0 = v0 ? r0 : 0, c1 = v1 ? r1 : 0;
        cp16(st + OFF_AH + swz(aRow0, kc), Ah + (size_t)c0 * K + kt + kc * 8, v0);
        cp16(st + OFF_AH + swz(aRow1, kc), Ah + (size_t)c1 * K + kt + kc * 8, v1);
        cp16(st + OFF_AL + swz(aRow0, kc), Al + (size_t)c0 * K + kt + kc * 8, v0);
        cp16(st + OFF_AL + swz(aRow1, kc), Al + (size_t)c1 * K + kt + kc * 8, v1);
        int br = bn + bRow;
        cp16(st + OFF_BH + swz(bRow, kc), Bh + (size_t)br * K + kt + kc * 8, true);
        cp16(st + OFF_BL + swz(bRow, kc), Bl + (size_t)br * K + kt + kc * 8, true);
        asm volatile("cp.async.commit_group;\n");
    }

    int lr = lane & 15, lc = lane >> 4;   // ldmatrix lane row / chunk-half

    for (int t = 0; t < nTiles; t++) {
        int buf = t & 1;
        if (t + 1 < nTiles) {
            int kt = kBeg + ((t + 1) << 5);
            uint32_t st = sbase + (buf ^ 1) * STG_BYTES;
            int r0 = bm + aRow0, r1 = bm + aRow1;
            bool v0 = r0 < M, v1 = r1 < M;
            int c0 = v0 ? r0 : 0, c1 = v1 ? r1 : 0;
            cp16(st + OFF_AH + swz(aRow0, kc), Ah + (size_t)c0 * K + kt + kc * 8, v0);
            cp16(st + OFF_AH + swz(aRow1, kc), Ah + (size_t)c1 * K + kt + kc * 8, v1);
            cp16(st + OFF_AL + swz(aRow0, kc), Al + (size_t)c0 * K + kt + kc * 8, v0);
            cp16(st + OFF_AL + swz(aRow1, kc), Al + (size_t)c1 * K + kt + kc * 8, v1);
            int br = bn + bRow;
            cp16(st + OFF_BH + swz(bRow, kc), Bh + (size_t)br * K + kt + kc * 8, true);
            cp16(st + OFF_BL + swz(bRow, kc), Bl + (size_t)br * K + kt + kc * 8, true);
            asm volatile("cp.async.commit_group;\n");
            asm volatile("cp.async.wait_group 1;\n");
        } else {
            asm volatile("cp.async.wait_group 0;\n");
        }
        __syncthreads();

        uint32_t st = sbase + buf * STG_BYTES;
#pragma unroll
        for (int kk = 0; kk < 2; kk++) {          // two k=16 slices
            int ch = kk * 2 + lc;                 // chunk for this lane
            uint32_t ah[2][4], al_[2][4], bh[2][4], bl[2][4];
#pragma unroll
            for (int mt = 0; mt < 2; mt++) {
                int row = wm + mt * 16 + lr;
                LDSM4(ah[mt],  st + OFF_AH + swz(row, ch));
                LDSM4(al_[mt], st + OFF_AL + swz(row, ch));
            }
#pragma unroll
            for (int pp = 0; pp < 2; pp++) {
                int row = wn + pp * 16 + lr;
                LDSM4(bh[pp], st + OFF_BH + swz(row, ch));
                LDSM4(bl[pp], st + OFF_BL + swz(row, ch));
            }
            // split-term outermost: no two consecutive MMAs share an accumulator
#pragma unroll
            for (int mt = 0; mt < 2; mt++)
#pragma unroll
                for (int pp = 0; pp < 2; pp++) {
                    MMA16816(acc[mt][pp * 2 + 0], ah[mt], bh[pp][0], bh[pp][2]);
                    MMA16816(acc[mt][pp * 2 + 1], ah[mt], bh[pp][1], bh[pp][3]);
                }
#pragma unroll
            for (int mt = 0; mt < 2; mt++)
#pragma unroll
                for (int pp = 0; pp < 2; pp++) {
                    MMA16816(acc[mt][pp * 2 + 0], ah[mt], bl[pp][0], bl[pp][2]);
                    MMA16816(acc[mt][pp * 2 + 1], ah[mt], bl[pp][1], bl[pp][3]);
                }
#pragma unroll
            for (int mt = 0; mt < 2; mt++)
#pragma unroll
                for (int pp = 0; pp < 2; pp++) {
                    MMA16816(acc[mt][pp * 2 + 0], al_[mt], bh[pp][0], bh[pp][2]);
                    MMA16816(acc[mt][pp * 2 + 1], al_[mt], bh[pp][1], bh[pp][3]);
                }
        }
        __syncthreads();
    }

    // epilogue
#pragma unroll
    for (int mt = 0; mt < 2; mt++) {
#pragma unroll
        for (int nt = 0; nt < 4; nt++) {
            int col = bn + wn + nt * 8 + 2 * tg;
            float bv0 = bias ? bias[col] : 0.f;
            float bv1 = bias ? bias[col + 1] : 0.f;
            int row0 = bm + wm + mt * 16 + g;
            if (row0 < M) {
                float2* p = (float2*)(C + (size_t)row0 * N + col);
                *p = make_float2(acc[mt][nt][0] + bv0, acc[mt][nt][1] + bv1);
            }
            int row1 = row0 + 8;
            if (row1 < M) {
                float2* p = (float2*)(C + (size_t)row1 * N + col);
                *p = make_float2(acc[mt][nt][2] + bv0, acc[mt][nt][3] + bv1);
            }
        }
    }
}

// ---------------- fixed-order reduction of 4 K-split partials ----------------
__global__ void reduce4(const float* __restrict__ p, float* __restrict__ out, int n) {
    int i = blockIdx.x * blockDim.x + threadIdx.x;
    if (i >= n) return;
    out[i] = ((p[i] + p[n + i]) + p[2 * n + i]) + p[3 * n + i];
}

// ---------------- rmsnorm + rope + transpose for q/k/v ----------------
__global__ void __launch_bounds__(128) qkv_prep(const float* __restrict__ h,
                                                const float* __restrict__ pe,
                                                const float* __restrict__ qns,
                                                const float* __restrict__ kns,
                                                float* __restrict__ qn,
                                                float* __restrict__ qr,
                                                float* __restrict__ kr,
                                                float* __restrict__ vr) {
    int head = blockIdx.x;
    int l = blockIdx.y;
    int d = threadIdx.x;
    const float* base = h + (size_t)l * N1 + head * DH;
    float qv = base[d];
    float kv = base[HID + d];
    float vv = base[2 * HID + d];
    float qss = qv * qv, kss = kv * kv;
#pragma unroll
    for (int o = 16; o; o >>= 1) {
        qss += __shfl_xor_sync(0xffffffffu, qss, o);
        kss += __shfl_xor_sync(0xffffffffu, kss, o);
    }
    __shared__ float rq[4], rk[4];
    if ((d & 31) == 0) { rq[d >> 5] = qss; rk[d >> 5] = kss; }
    __syncthreads();
    float qt = rq[0] + rq[1] + rq[2] + rq[3];
    float kt = rk[0] + rk[1] + rk[2] + rk[3];
    float qnv = qv * rsqrtf(qt * (1.f / DH) + EPSV) * qns[d];
    float knv = kv * rsqrtf(kt * (1.f / DH) + EPSV) * kns[d];
    __shared__ float sq[DH], sk[DH];
    sq[d] = qnv; sk[d] = knv;
    __syncthreads();
    int p = d >> 1, r = d & 1;
    const float* per = pe + (((size_t)l * 64 + p) * 2 + r) * 2;
    float qro = per[0] * sq[2 * p] + per[1] * sq[2 * p + 1];
    float kro = per[0] * sk[2 * p] + per[1] * sk[2 * p + 1];
    size_t o = ((size_t)head * LQ + l) * DH + d;
    qn[o] = qnv; qr[o] = qro; kr[o] = kro; vr[o] = vv;
}

// ---------------- flash attention (fp32, online softmax) ----------------
__global__ void __launch_bounds__(256) flash_kernel(const float* __restrict__ Q,
                                                    const float* __restrict__ Kp,
                                                    const float* __restrict__ Vp,
                                                    int Lk,
                                                    long long kv_head_stride,
                                                    long long kv_row_stride,
                                                    float* __restrict__ Out,
                                                    int accumulate,
                                                    const float* __restrict__ scale_ptr) {
    __shared__ float Ks[32][128];
    __shared__ float Vs[32][128];
    int head = blockIdx.y;
    int qtile = blockIdx.x;
    int tid = threadIdx.x;
    int i = tid >> 2;
    int g = tid & 3;
    int l = qtile * 64 + i;
    const float sm_scale = 0.08838834764831845f;

    float q[32];
    const float* qrow = Q + ((size_t)head * LQ + l) * DH + g * 32;
#pragma unroll
    for (int c = 0; c < 32; c++) q[c] = qrow[c] * sm_scale;

    float m = -INFINITY, lsum = 0.f;
    float acc[32];
#pragma unroll
    for (int c = 0; c < 32; c++) acc[c] = 0.f;

    const float* Kh = Kp + head * kv_head_stride;
    const float* Vh = Vp + head * kv_head_stride;

    for (int kv0 = 0; kv0 < Lk; kv0 += 32) {
        for (int idx = tid; idx < 32 * 32; idx += 256) {
            int r = idx >> 5, c4 = (idx & 31) * 4;
            const float* krow = Kh + (size_t)(kv0 + r) * kv_row_stride;
            const float* vrow = Vh + (size_t)(kv0 + r) * kv_row_stride;
            *(float4*)&Ks[r][c4] = *(const float4*)(krow + c4);
            *(float4*)&Vs[r][c4] = *(const float4*)(vrow + c4);
        }
        __syncthreads();
        for (int j = 0; j < 32; j++) {
            float s = 0.f;
            const float* kr_ = &Ks[j][g * 32];
#pragma unroll
            for (int c = 0; c < 32; c++) s += q[c] * kr_[c];
            s += __shfl_xor_sync(0xffffffffu, s, 1);
            s += __shfl_xor_sync(0xffffffffu, s, 2);
            float mnew = fmaxf(m, s);
            if (mnew > m) {
                float f = __expf(m - mnew);
                lsum *= f;
#pragma unroll
                for (int c = 0; c < 32; c++) acc[c] *= f;
                m = mnew;
            }
            float p = __expf(s - m);
            lsum += p;
            const float* vr_ = &Vs[j][g * 32];
#pragma unroll
            for (int c = 0; c < 32; c++) acc[c] += p * vr_[c];
        }
        __syncthreads();
    }
    float inv = 1.f / lsum;
    float* orow = Out + (size_t)l * HID + head * DH + g * 32;
    if (accumulate) {
        float sc = *scale_ptr;
#pragma unroll
        for (int c = 0; c < 32; c++) orow[c] += sc * acc[c] * inv;
    } else {
#pragma unroll
        for (int c = 0; c < 32; c++) orow[c] = acc[c] * inv;
    }
}

// ---------------- fused = [attn_out, gelu(mlp)] -> bf16 hi/lo ----------------
__global__ void fuse_gelu(const float* __restrict__ attn,
                          const float* __restrict__ h,
                          __nv_bfloat16* __restrict__ fh,
                          __nv_bfloat16* __restrict__ fl) {
    size_t idx = (size_t)blockIdx.x * blockDim.x + threadIdx.x;
    if (idx >= (size_t)LQ * KF) return;
    int l = (int)(idx / KF);
    int j = (int)(idx % KF);
    float f;
    if (j < HID) {
        f = attn[(size_t)l * HID + j];
    } else {
        float v = h[(size_t)l * N1 + 3 * HID + (j - HID)];
        float v3 = v * v * v;
        f = 0.5f * v * (1.f + tanhf(0.7978845608028654f * (v + 0.044715f * v3)));
    }
    __nv_bfloat16 hh = __float2bfloat16(f);
    fh[idx] = hh;
    fl[idx] = __float2bfloat16(f - __bfloat162float(hh));
}

// ---------------- residual: out = x + gate * tmp ----------------
__global__ void final_kernel(const float* __restrict__ x,
                             const float* __restrict__ mod,
                             const float* __restrict__ tmp,
                             float* __restrict__ out) {
    size_t idx = (size_t)blockIdx.x * blockDim.x + threadIdx.x;
    if (idx >= (size_t)LQ * HID) return;
    int c = (int)(idx % HID);
    out[idx] = x[idx] + mod[2 * HID + c] * tmp[idx];
}

// ---------------- launch ----------------
extern "C" void kernel_launch(void* const* d_in, const int* in_sizes, int n_in,
                              void* d_out, int out_size) {
    const float* x          = (const float*)d_in[0];
    const float* vec        = (const float*)d_in[1];
    const float* pe         = (const float*)d_in[2];
    const float* image_proj = (const float*)d_in[3];
    const float* ip_scale   = (const float*)d_in[4];
    const float* mod_w      = (const float*)d_in[5];
    const float* mod_b      = (const float*)d_in[6];
    const float* w1         = (const float*)d_in[7];
    const float* b1         = (const float*)d_in[8];
    const float* w2         = (const float*)d_in[9];
    const float* b2         = (const float*)d_in[10];
    const float* qns        = (const float*)d_in[11];
    const float* kns        = (const float*)d_in[12];
    const float* ipkw       = (const float*)d_in[13];
    const float* ipvw       = (const float*)d_in[14];
    float* out = (float*)d_out;

    float *mod, *h, *qn, *qr, *kr, *vr, *attn, *ipk, *ipv, *tmp, *ipkp, *ipvp;
    __nv_bfloat16 *xmh, *xml, *w1h, *w1l, *w2h, *w2l, *fuh, *ful;
    __nv_bfloat16 *iph, *ipl, *ipkh, *ipkl, *ipvh, *ipvl;
    cudaGetSymbolAddress((void**)&mod, g_mod);
    cudaGetSymbolAddress((void**)&h, g_h);
    cudaGetSymbolAddress((void**)&qn, g_qn);
    cudaGetSymbolAddress((void**)&qr, g_qr);
    cudaGetSymbolAddress((void**)&kr, g_kr);
    cudaGetSymbolAddress((void**)&vr, g_vr);
    cudaGetSymbolAddress((void**)&attn, g_attn);
    cudaGetSymbolAddress((void**)&ipk, g_ipk);
    cudaGetSymbolAddress((void**)&ipv, g_ipv);
    cudaGetSymbolAddress((void**)&tmp, g_tmp);
    cudaGetSymbolAddress((void**)&ipkp, g_ipkp);
    cudaGetSymbolAddress((void**)&ipvp, g_ipvp);
    cudaGetSymbolAddress((void**)&xmh, g_xmh);
    cudaGetSymbolAddress((void**)&xml, g_xml);
    cudaGetSymbolAddress((void**)&w1h, g_w1h);
    cudaGetSymbolAddress((void**)&w1l, g_w1l);
    cudaGetSymbolAddress((void**)&w2h, g_w2h);
    cudaGetSymbolAddress((void**)&w2l, g_w2l);
    cudaGetSymbolAddress((void**)&fuh, g_fuh);
    cudaGetSymbolAddress((void**)&ful, g_ful);
    cudaGetSymbolAddress((void**)&iph, g_iph);
    cudaGetSymbolAddress((void**)&ipl, g_ipl);
    cudaGetSymbolAddress((void**)&ipkh, g_ipkh);
    cudaGetSymbolAddress((void**)&ipkl, g_ipkl);
    cudaGetSymbolAddress((void**)&ipvh, g_ipvh);
    cudaGetSymbolAddress((void**)&ipvl, g_ipvl);

    // Launch order note: launch #4 (1-based) is the one ncu's -s window
    // captures — keep the big linear1 GEMM there.
    // #1: split w1
    {
        size_t n4 = (size_t)N1 * HID / 4;
        split_bf16_v4<<<(unsigned)((n4 + 255) / 256), 256>>>((const float4*)w1, (__nv_bfloat162*)w1h, (__nv_bfloat162*)w1l, n4);
    }
    // #2: fused silu + gemv
    mod_gemv<<<3 * HID, 128>>>(vec, mod_w, mod_b, mod);
    // #3: layernorm + modulation -> bf16 split activations
    ln_mod<<<LQ, 256>>>(x, mod, xmh, xml);
    // #4: h = x_mod @ W1^T + b1 : (2048, 21504), K=3072   [ncu capture slot]
    mma_gemm<<<dim3(LQ / 128, N1 / 64), 256>>>(LQ, N1, HID, 0, xmh, xml, w1h, w1l, b1, h);

    // remaining splits
    {
        size_t n4;
        n4 = (size_t)HID * KF / 4;
        split_bf16_v4<<<(unsigned)((n4 + 255) / 256), 256>>>((const float4*)w2, (__nv_bfloat162*)w2h, (__nv_bfloat162*)w2l, n4);
        n4 = (size_t)LIPN * CTX / 4;
        split_bf16_v4<<<(unsigned)((n4 + 255) / 256), 256>>>((const float4*)image_proj, (__nv_bfloat162*)iph, (__nv_bfloat162*)ipl, n4);
        n4 = (size_t)HID * CTX / 4;
        split_bf16_v4<<<(unsigned)((n4 + 255) / 256), 256>>>((const float4*)ipkw, (__nv_bfloat162*)ipkh, (__nv_bfloat162*)ipkl, n4);
        split_bf16_v4<<<(unsigned)((n4 + 255) / 256), 256>>>((const float4*)ipvw, (__nv_bfloat162*)ipvh, (__nv_bfloat162*)ipvl, n4);
    }

    qkv_prep<<<dim3(NH, LQ), 128>>>(h, pe, qns, kns, qn, qr, kr, vr);

    // ip_k / ip_v : (64, 3072) = image_proj @ W^T, K=4096 — K-split x4 for occupancy
    mma_gemm<<<dim3(1, HID / 64, 4), 256>>>(LIPN, HID, CTX, CTX / 4, iph, ipl, ipkh, ipkl, nullptr, ipkp);
    mma_gemm<<<dim3(1, HID / 64, 4), 256>>>(LIPN, HID, CTX, CTX / 4, iph, ipl, ipvh, ipvl, nullptr, ipvp);
    reduce4<<<(LIPN * HID + 255) / 256, 256>>>(ipkp, ipk, LIPN * HID);
    reduce4<<<(LIPN * HID + 255) / 256, 256>>>(ipvp, ipv, LIPN * HID);

    // self-attention (roped q/k)
    flash_kernel<<<dim3(LQ / 64, NH), 256>>>(qr, kr, vr, LQ,
                                             (long long)LQ * DH, (long long)DH,
                                             attn, 0, nullptr);
    // ip attention (un-roped q vs ip_k/ip_v), accumulates ip_scale * result
    flash_kernel<<<dim3(LQ / 64, NH), 256>>>(qn, ipk, ipv, LIPN,
                                             (long long)DH, (long long)HID,
                                             attn, 1, ip_scale);

    fuse_gelu<<<(LQ * KF + 255) / 256, 256>>>(attn, h, fuh, ful);

    // out_tmp = fused @ W2^T + b2 : (2048, 3072), K=15360
    mma_gemm<<<dim3(LQ / 128, HID / 64), 256>>>(LQ, HID, KF, 0, fuh, ful, w2h, w2l, b2, tmp);

    final_kernel<<<(LQ * HID + 255) / 256, 256>>>(x, mod, tmp, out);
}